// round 5
// baseline (speedup 1.0000x reference)
#include <cuda_runtime.h>
#include <cstdint>
#include <cstddef>

// ============================ problem constants =============================
namespace cfg {
constexpr int B  = 512;
constexpr int C  = 200;
constexpr int E  = 128;
constexpr int CV = 384;
constexpr int F  = 384;                 // K dim (3E)
constexpr int ROWS = B * C;             // 102400
constexpr int NTILES = ROWS / 128;      // 800
constexpr int NTH = 256;                // 8 warps: 4 (M) x 2 (N)

constexpr int PITCH = 400;              // bytes/row for int8 planes (384+16)

// dynamic smem layout (bytes)
constexpr uint32_t AQH = 0;             // A hi plane [128][400] int8 = 51200
constexpr uint32_t AQL = 51200;
constexpr uint32_t BQH = 102400;        // B hi plane (one nt) [128][400]
constexpr uint32_t BQL = 153600;
constexpr uint32_t SSC = 204800;        // 384 floats: delta_a*delta_b[v]
constexpr uint32_t IDX = 206336;        // 384 ints
constexpr uint32_t RED = 207872;        // 128 floats
constexpr uint32_t SMEM_BYTES = 208384;

constexpr float AMAX = 0.15f;           // clamp for ctx values (7.5 sigma)
constexpr float QMAX = 16319.f;         // 127*128 + 63
}

// ===================== device scratch (no runtime alloc) ====================
__device__ int8_t g_Wqh[cfg::CV * cfg::F];     // W hi int8, [v][k]
__device__ int8_t g_Wql[cfg::CV * cfg::F];     // W lo int8
__device__ float  g_sb[cfg::CV];               // delta_a * delta_b[v]
__device__ float  g_h[(size_t)cfg::ROWS * cfg::CV];
__device__ float  g_scores[cfg::ROWS];

// ============================== PTX helpers =================================
__device__ __forceinline__ uint32_t smem_u32(const void* p) {
    uint32_t a;
    asm("{ .reg .u64 t; cvta.to.shared.u64 t, %1; cvt.u32.u64 %0, t; }" : "=r"(a) : "l"(p));
    return a;
}
__device__ __forceinline__ void ldsm_x4(uint32_t (&r)[4], uint32_t addr) {
    asm volatile("ldmatrix.sync.aligned.m8n8.x4.shared.b16 {%0,%1,%2,%3}, [%4];"
                 : "=r"(r[0]), "=r"(r[1]), "=r"(r[2]), "=r"(r[3]) : "r"(addr));
}
__device__ __forceinline__ void mma_s8(int (&d)[4], const uint32_t (&a)[4],
                                       uint32_t b0, uint32_t b1) {
    asm volatile(
        "mma.sync.aligned.m16n8k32.row.col.s32.s8.s8.s32 "
        "{%0,%1,%2,%3}, {%4,%5,%6,%7}, {%8,%9}, {%0,%1,%2,%3};"
        : "+r"(d[0]), "+r"(d[1]), "+r"(d[2]), "+r"(d[3])
        : "r"(a[0]), "r"(a[1]), "r"(a[2]), "r"(a[3]), "r"(b0), "r"(b1));
}
__device__ __forceinline__ void cp_async16(uint32_t dst, const void* src) {
    asm volatile("cp.async.cg.shared.global [%0], [%1], 16;"
                 :: "r"(dst), "l"(src) : "memory");
}
__device__ __forceinline__ void cp_commit() {
    asm volatile("cp.async.commit_group;" ::: "memory");
}
__device__ __forceinline__ void cp_wait0() {
    asm volatile("cp.async.wait_group 0;" ::: "memory");
}
// quantize fp32 -> (h, l) with q = 128h + l, h in [-127,127], l in [-64,63]
__device__ __forceinline__ void quant(float x, float scale, int& h, int& l) {
    float qf = fminf(fmaxf(x * scale, -cfg::QMAX), cfg::QMAX);
    int q = __float2int_rn(qf);
    h = (q + 64) >> 7;
    l = q - (h << 7);
}
__device__ __forceinline__ uint32_t pack4(int a, int b, int c, int d) {
    return (uint32_t)(a & 0xFF) | ((uint32_t)(b & 0xFF) << 8) |
           ((uint32_t)(c & 0xFF) << 16) | ((uint32_t)(d & 0xFF) << 24);
}

// ================= kernel 0: W fp32 -> int8 hi/lo + per-row scale ===========
__global__ void __launch_bounds__(128)
wq_kernel(const float* __restrict__ W) {
    const int v = blockIdx.x;            // 384 rows
    const int tid = threadIdx.x;
    __shared__ float red[4];
    __shared__ float s_inv;

    float m = 1e-20f;
    for (int k = tid; k < cfg::F; k += 128)
        m = fmaxf(m, fabsf(W[v * cfg::F + k]));
    #pragma unroll
    for (int o = 16; o; o >>= 1) m = fmaxf(m, __shfl_xor_sync(~0u, m, o));
    if ((tid & 31) == 0) red[tid >> 5] = m;
    __syncthreads();
    if (tid == 0) {
        float mm = fmaxf(fmaxf(red[0], red[1]), fmaxf(red[2], red[3]));
        s_inv = cfg::QMAX / mm;
        g_sb[v] = (cfg::AMAX / cfg::QMAX) * (mm / cfg::QMAX);
    }
    __syncthreads();
    const float inv = s_inv;
    for (int k4 = tid; k4 < cfg::F / 4; k4 += 128) {
        float4 x = ((const float4*)(W + v * cfg::F))[k4];
        int h0, l0, h1, l1, h2, l2, h3, l3;
        quant(x.x, inv, h0, l0);
        quant(x.y, inv, h1, l1);
        quant(x.z, inv, h2, l2);
        quant(x.w, inv, h3, l3);
        ((uint32_t*)g_Wqh)[v * (cfg::F / 4) + k4] = pack4(h0, h1, h2, h3);
        ((uint32_t*)g_Wql)[v * (cfg::F / 4) + k4] = pack4(l0, l1, l2, l3);
    }
}

// ====== kernel 1: gather + int8x3 IMMA GEMM + tanh + h + scores =============
__global__ void __launch_bounds__(cfg::NTH, 1)
k1_mma_kernel(const int* __restrict__ starts,
              const int* __restrict__ paths,
              const int* __restrict__ ends,
              const float* __restrict__ node_emb,
              const float* __restrict__ path_emb,
              const float* __restrict__ avec) {
    using namespace cfg;
    extern __shared__ char smem[];
    const uint32_t sb = smem_u32(smem);
    const int tid = threadIdx.x;
    const int wid = tid >> 5, lane = tid & 31;
    const int wm = wid & 3;              // M slice (32 rows)
    const int wn = wid >> 2;             // N slice (64 cols of 128-chunk)
    const int tile = blockIdx.x;
    int* sidx = (int*)(smem + IDX);
    float* red = (float*)(smem + RED);
    float* ssc = (float*)(smem + SSC);

    // ---- indices ----
    if (tid < 128) {
        int r = tile * 128 + tid;
        sidx[tid]       = starts[r];
        sidx[128 + tid] = paths[r];
        sidx[256 + tid] = ends[r];
    }
    __syncthreads();

    // ---- stage B planes (async). 3072 16B-chunks per plane. ----
    auto stageB = [&](int nt) {
        #pragma unroll
        for (int i = 0; i < 24; ++i) {
            const int mat = (i >= 12);               // 0=hi, 1=lo
            int t = tid + (i - mat * 12) * 256;      // 0..3071 within plane
            int n = t / 24, ch = t % 24;             // row, 16B chunk
            const int8_t* src = (mat ? g_Wql : g_Wqh) +
                                (size_t)(nt * 128 + n) * 384 + ch * 16;
            cp_async16(sb + (mat ? BQL : BQH) + n * PITCH + ch * 16, src);
        }
        cp_commit();
    };
    stageB(0);

    // ---- per-v combined scales into smem ----
    if (tid < 128) {
        ssc[tid]       = g_sb[tid];
        ssc[128 + tid] = g_sb[128 + tid];
        ssc[256 + tid] = g_sb[256 + tid];
    }

    // ---- gather ctx rows, quantize to int8 hi/lo planes ----
    const float QS = QMAX / AMAX;
    #pragma unroll 2
    for (int i = 0; i < 48; ++i) {
        int task = tid + i * 256;                // 0..12287
        int j = task & 31;                       // float4 within 128-elem row
        int rem = task >> 5;
        int seg = rem % 3, row = rem / 3;
        int idx = sidx[seg * 128 + row];
        const float4* src = (seg == 1) ? (const float4*)path_emb
                                       : (const float4*)node_emb;
        float4 x = __ldg(src + (size_t)idx * 32 + j);
        int h0, l0, h1, l1, h2, l2, h3, l3;
        quant(x.x, QS, h0, l0);
        quant(x.y, QS, h1, l1);
        quant(x.z, QS, h2, l2);
        quant(x.w, QS, h3, l3);
        int k = seg * 128 + j * 4;
        uint32_t off = (uint32_t)row * PITCH + (uint32_t)k;
        *(uint32_t*)(smem + AQH + off) = pack4(h0, h1, h2, h3);
        *(uint32_t*)(smem + AQL + off) = pack4(l0, l1, l2, l3);
    }

    // ---- ldmatrix lane addresses ----
    const uint32_t a_lane = sb + (uint32_t)(wm * 32 + (lane & 15)) * PITCH
                          + (uint32_t)(lane >> 4) * 16;
    const int bgrp = lane >> 3;
    const uint32_t b_lane = sb + (uint32_t)(((bgrp & 2) << 2) + (lane & 7)) * PITCH
                          + (uint32_t)(bgrp & 1) * 16;

    float sc[2][2] = {{0.f, 0.f}, {0.f, 0.f}};   // score partials [mi][rowhalf]
    const size_t rowbase = (size_t)tile * 128;

    cp_wait0();
    __syncthreads();                              // A + B(0) ready

    for (int nt = 0; nt < 3; ++nt) {
        int hh[2][8][4], cr[2][8][4];
        #pragma unroll
        for (int mi = 0; mi < 2; ++mi)
            #pragma unroll
            for (int ni = 0; ni < 8; ++ni)
                #pragma unroll
                for (int q = 0; q < 4; ++q) { hh[mi][ni][q] = 0; cr[mi][ni][q] = 0; }

        // ---- 12 k32 steps, no barriers ----
        #pragma unroll 2
        for (int st = 0; st < 12; ++st) {
            const uint32_t ak = (uint32_t)st * 32;
            uint32_t ah[2][4], al[2][4];
            #pragma unroll
            for (int mi = 0; mi < 2; ++mi) {
                ldsm_x4(ah[mi], a_lane + AQH + mi * (16 * PITCH) + ak);
                ldsm_x4(al[mi], a_lane + AQL + mi * (16 * PITCH) + ak);
            }
            #pragma unroll
            for (int bj = 0; bj < 4; ++bj) {
                const uint32_t bn = (uint32_t)(wn * 64 + bj * 16) * PITCH + ak;
                uint32_t rh[4], rl[4];
                ldsm_x4(rh, b_lane + BQH + bn);
                ldsm_x4(rl, b_lane + BQL + bn);
                #pragma unroll
                for (int mi = 0; mi < 2; ++mi) {
                    mma_s8(hh[mi][2*bj],   ah[mi], rh[0], rh[1]);
                    mma_s8(hh[mi][2*bj+1], ah[mi], rh[2], rh[3]);
                    mma_s8(cr[mi][2*bj],   ah[mi], rl[0], rl[1]);
                    mma_s8(cr[mi][2*bj+1], ah[mi], rl[2], rl[3]);
                    mma_s8(cr[mi][2*bj],   al[mi], rh[0], rh[1]);
                    mma_s8(cr[mi][2*bj+1], al[mi], rh[2], rh[3]);
                }
            }
        }

        __syncthreads();                          // B planes free for re-stage
        if (nt < 2) stageB(nt + 1);               // overlaps epilogue below

        // ---- epilogue: dequant, tanh, h store, score partials ----
        #pragma unroll
        for (int mi = 0; mi < 2; ++mi) {
            const int r0 = wm * 32 + mi * 16 + (lane >> 2);
            #pragma unroll
            for (int ni = 0; ni < 8; ++ni) {
                const int v0 = nt * 128 + wn * 64 + ni * 8 + (lane & 3) * 2;
                const float s0 = ssc[v0], s1 = ssc[v0 + 1];
                const float a0v = __ldg(avec + v0);
                const float a1v = __ldg(avec + v0 + 1);
                float d00 = s0 * (16384.f * (float)hh[mi][ni][0] + 128.f * (float)cr[mi][ni][0]);
                float d01 = s1 * (16384.f * (float)hh[mi][ni][1] + 128.f * (float)cr[mi][ni][1]);
                float d10 = s0 * (16384.f * (float)hh[mi][ni][2] + 128.f * (float)cr[mi][ni][2]);
                float d11 = s1 * (16384.f * (float)hh[mi][ni][3] + 128.f * (float)cr[mi][ni][3]);
                float h00 = tanhf(d00), h01 = tanhf(d01);
                float h10 = tanhf(d10), h11 = tanhf(d11);
                *(float2*)(g_h + (rowbase + r0) * 384 + v0)     = make_float2(h00, h01);
                *(float2*)(g_h + (rowbase + r0 + 8) * 384 + v0) = make_float2(h10, h11);
                sc[mi][0] += h00 * a0v + h01 * a1v;
                sc[mi][1] += h10 * a0v + h11 * a1v;
            }
        }

        if (nt < 2) {
            cp_wait0();
            __syncthreads();                      // B(nt+1) visible
        }
    }

    // ---- score reduction: quad shfl, then cross-warp over wn ----
    #pragma unroll
    for (int mi = 0; mi < 2; ++mi)
        #pragma unroll
        for (int j = 0; j < 2; ++j) {
            float s = sc[mi][j];
            s += __shfl_xor_sync(0xFFFFFFFFu, s, 1);
            s += __shfl_xor_sync(0xFFFFFFFFu, s, 2);
            sc[mi][j] = s;
        }
    __syncthreads();
    if (wn == 1 && (lane & 3) == 0) {
        #pragma unroll
        for (int mi = 0; mi < 2; ++mi)
            #pragma unroll
            for (int j = 0; j < 2; ++j)
                red[wm * 32 + mi * 16 + j * 8 + (lane >> 2)] = sc[mi][j];
    }
    __syncthreads();
    if (wn == 0 && (lane & 3) == 0) {
        #pragma unroll
        for (int mi = 0; mi < 2; ++mi)
            #pragma unroll
            for (int j = 0; j < 2; ++j) {
                int lr = wm * 32 + mi * 16 + j * 8 + (lane >> 2);
                g_scores[rowbase + lr] = sc[mi][j] + red[lr];
            }
    }
}

// ================= kernel 2: softmax over C + weighted sum ==================
__global__ void __launch_bounds__(cfg::CV)
k2_softmax_kernel(float* __restrict__ out) {
    using namespace cfg;
    const int b = blockIdx.x;
    const int tid = threadIdx.x;

    __shared__ float scs[C];
    __shared__ float attn[C];
    __shared__ float red[32];
    __shared__ float s_max, s_sum;

    if (tid < C) scs[tid] = g_scores[b * C + tid];
    __syncthreads();

    if (tid < 32) {
        float m = -3.4e38f;
        for (int c = tid; c < C; c += 32) m = fmaxf(m, scs[c]);
        red[tid] = m;
    }
    __syncthreads();
    if (tid == 0) {
        float m = red[0];
        #pragma unroll
        for (int j = 1; j < 32; ++j) m = fmaxf(m, red[j]);
        s_max = m;
    }
    __syncthreads();
    if (tid < 32) {
        float s = 0.f;
        for (int c = tid; c < C; c += 32) s += expf(scs[c] - s_max);
        red[tid] = s;
    }
    __syncthreads();
    if (tid == 0) {
        float s = 0.f;
        #pragma unroll
        for (int j = 0; j < 32; ++j) s += red[j];
        s_sum = s;
    }
    __syncthreads();
    if (tid < C) attn[tid] = expf(scs[tid] - s_max) / s_sum;
    __syncthreads();

    const float* hb = g_h + (size_t)b * C * CV;
    const int v = tid;
    float a0 = 0.f, a1 = 0.f, a2 = 0.f, a3 = 0.f;
    #pragma unroll 4
    for (int c = 0; c < C; c += 4) {
        a0 = fmaf(attn[c + 0], hb[(size_t)(c + 0) * CV + v], a0);
        a1 = fmaf(attn[c + 1], hb[(size_t)(c + 1) * CV + v], a1);
        a2 = fmaf(attn[c + 2], hb[(size_t)(c + 2) * CV + v], a2);
        a3 = fmaf(attn[c + 3], hb[(size_t)(c + 3) * CV + v], a3);
    }
    out[(size_t)b * CV + v] = (a0 + a1) + (a2 + a3);
}

// ================================ launch =====================================
extern "C" void kernel_launch(void* const* d_in, const int* in_sizes, int n_in,
                              void* d_out, int out_size) {
    (void)in_sizes; (void)n_in; (void)out_size;
    const int*   starts   = (const int*)d_in[0];
    const int*   paths    = (const int*)d_in[1];
    const int*   ends     = (const int*)d_in[2];
    /* masks d_in[3] unused by the reference */
    const float* node_emb = (const float*)d_in[4];
    const float* path_emb = (const float*)d_in[5];
    const float* W        = (const float*)d_in[6];
    const float* avec     = (const float*)d_in[7];
    float* out = (float*)d_out;

    cudaFuncSetAttribute(k1_mma_kernel,
                         cudaFuncAttributeMaxDynamicSharedMemorySize,
                         (int)cfg::SMEM_BYTES);

    wq_kernel<<<cfg::CV, 128>>>(W);
    k1_mma_kernel<<<cfg::NTILES, cfg::NTH, cfg::SMEM_BYTES>>>(
        starts, paths, ends, node_emb, path_emb, avec);
    k2_softmax_kernel<<<cfg::B, cfg::CV>>>(out);
}

// round 6
// speedup vs baseline: 2.0149x; 2.0149x over previous
#include <cuda_runtime.h>
#include <cstdint>
#include <cstddef>

// ============================ problem constants =============================
namespace cfg {
constexpr int B  = 512;
constexpr int C  = 200;
constexpr int E  = 128;
constexpr int CV = 384;
constexpr int F  = 384;                 // K dim (3E)
constexpr int ROWS = B * C;             // 102400
constexpr int NTILES = ROWS / 128;      // 800
constexpr int NTH = 256;                // 8 warps: 4 (M) x 2 (N)

// dynamic smem layout (bytes)
// A: [128 rows][384 tf32] = 1536 B/row, XOR-swizzled at 16B granularity
constexpr uint32_t A_OFF = 0;            // 196608
constexpr uint32_t B0    = 196608;       // [128 n][32 k tf32] = 16384, swizzled
constexpr uint32_t B1    = 212992;       // 16384
constexpr uint32_t SMEM_BYTES = 229376;
// idx (1536 B) lives in B1 during gather; red (512 B) in B0 after mainloop.
constexpr int NCHUNK = 36;               // 3 nt x 12 kc
}

// ===================== device scratch (no runtime alloc) ====================
__device__ uint32_t g_Wt32[cfg::CV * cfg::F];        // W as tf32 bits, [v][k]
__device__ float    g_h[(size_t)cfg::ROWS * cfg::CV];
__device__ float    g_scores[cfg::ROWS];

// ============================== PTX helpers =================================
__device__ __forceinline__ uint32_t smem_u32(const void* p) {
    uint32_t a;
    asm("{ .reg .u64 t; cvta.to.shared.u64 t, %1; cvt.u32.u64 %0, t; }" : "=r"(a) : "l"(p));
    return a;
}
__device__ __forceinline__ uint32_t tf32rna(float x) {
    uint32_t r;
    asm("cvt.rna.tf32.f32 %0, %1;" : "=r"(r) : "f"(x));
    return r;
}
__device__ __forceinline__ void mma_tf32(float (&d)[4],
                                         uint32_t a0, uint32_t a1,
                                         uint32_t a2, uint32_t a3,
                                         uint32_t b0, uint32_t b1) {
    asm volatile(
        "mma.sync.aligned.m16n8k8.row.col.f32.tf32.tf32.f32 "
        "{%0,%1,%2,%3}, {%4,%5,%6,%7}, {%8,%9}, {%0,%1,%2,%3};"
        : "+f"(d[0]), "+f"(d[1]), "+f"(d[2]), "+f"(d[3])
        : "r"(a0), "r"(a1), "r"(a2), "r"(a3), "r"(b0), "r"(b1));
}
__device__ __forceinline__ void cp_async16(uint32_t dst, const void* src) {
    asm volatile("cp.async.cg.shared.global [%0], [%1], 16;"
                 :: "r"(dst), "l"(src) : "memory");
}
__device__ __forceinline__ void cp_commit() {
    asm volatile("cp.async.commit_group;" ::: "memory");
}
__device__ __forceinline__ void cp_wait1() {
    asm volatile("cp.async.wait_group 1;" ::: "memory");
}
__device__ __forceinline__ uint32_t lds32(uint32_t addr) {
    uint32_t v;
    asm volatile("ld.shared.b32 %0, [%1];" : "=r"(v) : "r"(addr));
    return v;
}

// ================= kernel 0: W fp32 -> tf32 bits ([v][k] row-major) =========
__global__ void __launch_bounds__(256)
wconv_kernel(const float* __restrict__ W) {
    int i = blockIdx.x * 256 + threadIdx.x;          // float4 id, 36864 total
    float4 x = ((const float4*)W)[i];
    uint4 t;
    t.x = tf32rna(x.x);
    t.y = tf32rna(x.y);
    t.z = tf32rna(x.z);
    t.w = tf32rna(x.w);
    ((uint4*)g_Wt32)[i] = t;
}

// ====== kernel 1: gather + tf32 HMMA GEMM + tanh + h + scores ===============
__global__ void __launch_bounds__(cfg::NTH, 1)
k1_mma_kernel(const int* __restrict__ starts,
              const int* __restrict__ paths,
              const int* __restrict__ ends,
              const float* __restrict__ node_emb,
              const float* __restrict__ path_emb,
              const float* __restrict__ avec) {
    using namespace cfg;
    extern __shared__ char smem[];
    const uint32_t sb = smem_u32(smem);
    const int tid = threadIdx.x;
    const int wid = tid >> 5, lane = tid & 31;
    const int wm = wid & 3;              // M slice (32 rows)
    const int wn = wid >> 2;             // N slice (64 cols of 128-chunk)
    const int tile = blockIdx.x;
    int* sidx = (int*)(smem + B1);       // idx lives in B1 until first B1 stage

    // ---- indices ----
    if (tid < 128) {
        int r = tile * 128 + tid;
        sidx[tid]       = starts[r];
        sidx[128 + tid] = paths[r];
        sidx[256 + tid] = ends[r];
    }
    __syncthreads();

    // ---- B chunk staging (cp.async, swizzled dst) ----
    auto stageB = [&](int q, uint32_t buf) {
        const int nt = q / 12, kc = q % 12;
        #pragma unroll
        for (int i = 0; i < 4; ++i) {
            int t = tid + i * 256;                   // 0..1023
            int n = t >> 3, ch = t & 7;              // row, 16B chunk of 32-k
            const uint32_t* src = g_Wt32 +
                ((size_t)(nt * 128 + n) * 384 + kc * 32 + ch * 4);
            cp_async16(sb + buf + n * 128 + ((uint32_t)(ch ^ (n & 7)) << 4), src);
        }
        cp_commit();
    };
    stageB(0, B0);                                   // G0 (overlaps gather)

    // ---- gather ctx rows -> tf32 into swizzled A ----
    #pragma unroll 2
    for (int i = 0; i < 48; ++i) {
        int task = tid + i * 256;                    // 0..12287
        int j = task & 31;                           // float4 within 128-elem row
        int rem = task >> 5;
        int seg = rem % 3, row = rem / 3;
        int idx = sidx[seg * 128 + row];
        const float4* src = (seg == 1) ? (const float4*)path_emb
                                       : (const float4*)node_emb;
        float4 x = __ldg(src + (size_t)idx * 32 + j);
        uint4 t;
        t.x = tf32rna(x.x);
        t.y = tf32rna(x.y);
        t.z = tf32rna(x.z);
        t.w = tf32rna(x.w);
        int ch = seg * 32 + j;                       // 16B chunk index 0..95
        *(uint4*)(smem + A_OFF + (uint32_t)row * 1536 +
                  ((uint32_t)(ch ^ (row & 7)) << 4)) = t;
    }
    __syncthreads();
    stageB(1, B1);                                   // G1 (overwrites idx; safe)

    // ---- per-thread constant addressing ----
    const int g = lane >> 2;                         // group id 0..7
    const int c4 = (lane & 3) * 4;                   // byte offset within 16B
    const uint32_t sw = (uint32_t)(g & 7);           // XOR swizzle key
    // A row bases: rows r = wm*32 + mi*16 + half*8 + g  (r&7 == g&7 always)
    uint32_t a_base[2][2];
    #pragma unroll
    for (int mi = 0; mi < 2; ++mi)
        #pragma unroll
        for (int hf = 0; hf < 2; ++hf)
            a_base[mi][hf] = sb + A_OFF +
                (uint32_t)(wm * 32 + mi * 16 + hf * 8 + g) * 1536 + c4;
    // B row bases: n = wn*64 + ni*8 + g
    uint32_t b_base[8];
    #pragma unroll
    for (int ni = 0; ni < 8; ++ni)
        b_base[ni] = (uint32_t)(wn * 64 + ni * 8 + g) * 128 + c4;

    float sc[2][2] = {{0.f, 0.f}, {0.f, 0.f}};       // score partials [mi][half]
    const size_t rowbase = (size_t)tile * 128;

    for (int nt = 0; nt < 3; ++nt) {
        float acc[2][8][4];
        #pragma unroll
        for (int mi = 0; mi < 2; ++mi)
            #pragma unroll
            for (int ni = 0; ni < 8; ++ni)
                #pragma unroll
                for (int q = 0; q < 4; ++q) acc[mi][ni][q] = 0.f;

        for (int kc = 0; kc < 12; ++kc) {
            const int q = nt * 12 + kc;
            const uint32_t buf = sb + ((q & 1) ? B1 : B0);
            cp_wait1();                              // chunk q's group done
            __syncthreads();

            #pragma unroll
            for (int ks = 0; ks < 4; ++ks) {         // 4 k8 steps in 32-k chunk
                const uint32_t achunk = (uint32_t)((kc * 4 + ks) * 2);
                const uint32_t a_k0 = ((achunk)     ^ sw) << 4;
                const uint32_t a_k1 = ((achunk + 1) ^ sw) << 4;
                const uint32_t bchunk = (uint32_t)(ks * 2);
                const uint32_t b_k0 = ((bchunk)     ^ sw) << 4;
                const uint32_t b_k1 = ((bchunk + 1) ^ sw) << 4;

                uint32_t a[2][4];
                #pragma unroll
                for (int mi = 0; mi < 2; ++mi) {
                    a[mi][0] = lds32(a_base[mi][0] + a_k0);
                    a[mi][1] = lds32(a_base[mi][1] + a_k0);
                    a[mi][2] = lds32(a_base[mi][0] + a_k1);
                    a[mi][3] = lds32(a_base[mi][1] + a_k1);
                }
                #pragma unroll
                for (int ni = 0; ni < 8; ++ni) {
                    uint32_t b0 = lds32(buf + b_base[ni] + b_k0);
                    uint32_t b1 = lds32(buf + b_base[ni] + b_k1);
                    mma_tf32(acc[0][ni], a[0][0], a[0][1], a[0][2], a[0][3], b0, b1);
                    mma_tf32(acc[1][ni], a[1][0], a[1][1], a[1][2], a[1][3], b0, b1);
                }
            }

            __syncthreads();                         // all reads of buf done
            if (q + 2 < NCHUNK) stageB(q + 2, (q & 1) ? B1 : B0);
            cp_commit();                             // one group per iter
        }

        // ---- epilogue: tanh, h store, score partials (overlaps next stage) --
        #pragma unroll
        for (int mi = 0; mi < 2; ++mi) {
            const int r0 = wm * 32 + mi * 16 + g;
            #pragma unroll
            for (int ni = 0; ni < 8; ++ni) {
                const int v0 = nt * 128 + wn * 64 + ni * 8 + (lane & 3) * 2;
                const float a0v = __ldg(avec + v0);
                const float a1v = __ldg(avec + v0 + 1);
                float h00 = tanhf(acc[mi][ni][0]);
                float h01 = tanhf(acc[mi][ni][1]);
                float h10 = tanhf(acc[mi][ni][2]);
                float h11 = tanhf(acc[mi][ni][3]);
                *(float2*)(g_h + (rowbase + r0) * 384 + v0)     = make_float2(h00, h01);
                *(float2*)(g_h + (rowbase + r0 + 8) * 384 + v0) = make_float2(h10, h11);
                sc[mi][0] += h00 * a0v + h01 * a1v;
                sc[mi][1] += h10 * a0v + h11 * a1v;
            }
        }
    }

    // ---- score reduction: quad shfl, then cross-warp over wn ----
    float* red = (float*)(smem + B0);                // mainloop done; B0 free
    #pragma unroll
    for (int mi = 0; mi < 2; ++mi)
        #pragma unroll
        for (int j = 0; j < 2; ++j) {
            float s = sc[mi][j];
            s += __shfl_xor_sync(0xFFFFFFFFu, s, 1);
            s += __shfl_xor_sync(0xFFFFFFFFu, s, 2);
            sc[mi][j] = s;
        }
    __syncthreads();
    if (wn == 1 && (lane & 3) == 0) {
        #pragma unroll
        for (int mi = 0; mi < 2; ++mi)
            #pragma unroll
            for (int j = 0; j < 2; ++j)
                red[wm * 32 + mi * 16 + j * 8 + g] = sc[mi][j];
    }
    __syncthreads();
    if (wn == 0 && (lane & 3) == 0) {
        #pragma unroll
        for (int mi = 0; mi < 2; ++mi)
            #pragma unroll
            for (int j = 0; j < 2; ++j) {
                int lr = wm * 32 + mi * 16 + j * 8 + g;
                g_scores[rowbase + lr] = sc[mi][j] + red[lr];
            }
    }
}

// ================= kernel 2: softmax over C + weighted sum ==================
__global__ void __launch_bounds__(cfg::CV)
k2_softmax_kernel(float* __restrict__ out) {
    using namespace cfg;
    const int b = blockIdx.x;
    const int tid = threadIdx.x;

    __shared__ float scs[C];
    __shared__ float attn[C];
    __shared__ float red[32];
    __shared__ float s_max, s_sum;

    if (tid < C) scs[tid] = g_scores[b * C + tid];
    __syncthreads();

    if (tid < 32) {
        float m = -3.4e38f;
        for (int c = tid; c < C; c += 32) m = fmaxf(m, scs[c]);
        red[tid] = m;
    }
    __syncthreads();
    if (tid == 0) {
        float m = red[0];
        #pragma unroll
        for (int j = 1; j < 32; ++j) m = fmaxf(m, red[j]);
        s_max = m;
    }
    __syncthreads();
    if (tid < 32) {
        float s = 0.f;
        for (int c = tid; c < C; c += 32) s += expf(scs[c] - s_max);
        red[tid] = s;
    }
    __syncthreads();
    if (tid == 0) {
        float s = 0.f;
        #pragma unroll
        for (int j = 0; j < 32; ++j) s += red[j];
        s_sum = s;
    }
    __syncthreads();
    if (tid < C) attn[tid] = expf(scs[tid] - s_max) / s_sum;
    __syncthreads();

    const float* hb = g_h + (size_t)b * C * CV;
    const int v = tid;
    float a0 = 0.f, a1 = 0.f, a2 = 0.f, a3 = 0.f;
    #pragma unroll 4
    for (int c = 0; c < C; c += 4) {
        a0 = fmaf(attn[c + 0], hb[(size_t)(c + 0) * CV + v], a0);
        a1 = fmaf(attn[c + 1], hb[(size_t)(c + 1) * CV + v], a1);
        a2 = fmaf(attn[c + 2], hb[(size_t)(c + 2) * CV + v], a2);
        a3 = fmaf(attn[c + 3], hb[(size_t)(c + 3) * CV + v], a3);
    }
    out[(size_t)b * CV + v] = (a0 + a1) + (a2 + a3);
}

// ================================ launch =====================================
extern "C" void kernel_launch(void* const* d_in, const int* in_sizes, int n_in,
                              void* d_out, int out_size) {
    (void)in_sizes; (void)n_in; (void)out_size;
    const int*   starts   = (const int*)d_in[0];
    const int*   paths    = (const int*)d_in[1];
    const int*   ends     = (const int*)d_in[2];
    /* masks d_in[3] unused by the reference */
    const float* node_emb = (const float*)d_in[4];
    const float* path_emb = (const float*)d_in[5];
    const float* W        = (const float*)d_in[6];
    const float* avec     = (const float*)d_in[7];
    float* out = (float*)d_out;

    cudaFuncSetAttribute(k1_mma_kernel,
                         cudaFuncAttributeMaxDynamicSharedMemorySize,
                         (int)cfg::SMEM_BYTES);

    wconv_kernel<<<cfg::CV * cfg::F / 4 / 256, 256>>>(W);
    k1_mma_kernel<<<cfg::NTILES, cfg::NTH, cfg::SMEM_BYTES>>>(
        starts, paths, ends, node_emb, path_emb, avec);
    k2_softmax_kernel<<<cfg::B, cfg::CV>>>(out);
}

// round 8
// speedup vs baseline: 2.6291x; 1.3048x over previous
#include <cuda_runtime.h>
#include <cuda_fp16.h>
#include <cstdint>
#include <cstddef>

// ============================ problem constants =============================
namespace cfg {
constexpr int B  = 512;
constexpr int C  = 200;
constexpr int E  = 128;
constexpr int CV = 384;
constexpr int F  = 384;                 // K dim (3E)
constexpr int ROWS = B * C;             // 102400
constexpr int NTILES = ROWS / 128;      // 800
constexpr int NTH = 256;                // 8 warps: 4 (M) x 2 (N)

constexpr int APAD = 392;               // A row: 384 + 8 fp16 -> 784 B
constexpr int BPAD = 40;                // B row: 32 + 8 fp16  -> 80 B

// dynamic smem layout (bytes)
constexpr uint32_t A_OFF = 0;            // [128][392] fp16 = 100352
constexpr uint32_t B0    = 100352;       // [128][40] fp16 = 10240
constexpr uint32_t B1    = 110592;       // 10240
constexpr uint32_t IDX   = 120832;       // 384 ints = 1536
constexpr uint32_t RED   = 122368;       // 128 floats = 512
constexpr uint32_t SMEM_BYTES = 122880;
constexpr int NCHUNK = 36;               // 3 nt x 12 kc
}

// ===================== device scratch (no runtime alloc) ====================
__device__ __half g_Wf16[cfg::CV * cfg::F];          // W fp16, [v][k] row-major
__device__ float  g_h[(size_t)cfg::ROWS * cfg::CV];
__device__ float  g_scores[cfg::ROWS];

// ============================== PTX helpers =================================
__device__ __forceinline__ uint32_t smem_u32(const void* p) {
    uint32_t a;
    asm("{ .reg .u64 t; cvta.to.shared.u64 t, %1; cvt.u32.u64 %0, t; }" : "=r"(a) : "l"(p));
    return a;
}
__device__ __forceinline__ void ldsm_x4(uint32_t (&r)[4], uint32_t addr) {
    asm volatile("ldmatrix.sync.aligned.m8n8.x4.shared.b16 {%0,%1,%2,%3}, [%4];"
                 : "=r"(r[0]), "=r"(r[1]), "=r"(r[2]), "=r"(r[3]) : "r"(addr));
}
__device__ __forceinline__ void mma_f16(float (&d)[4], const uint32_t (&a)[4],
                                        uint32_t b0, uint32_t b1) {
    asm volatile(
        "mma.sync.aligned.m16n8k16.row.col.f32.f16.f16.f32 "
        "{%0,%1,%2,%3}, {%4,%5,%6,%7}, {%8,%9}, {%0,%1,%2,%3};"
        : "+f"(d[0]), "+f"(d[1]), "+f"(d[2]), "+f"(d[3])
        : "r"(a[0]), "r"(a[1]), "r"(a[2]), "r"(a[3]), "r"(b0), "r"(b1));
}
__device__ __forceinline__ void cp_async16(uint32_t dst, const void* src) {
    asm volatile("cp.async.cg.shared.global [%0], [%1], 16;"
                 :: "r"(dst), "l"(src) : "memory");
}
__device__ __forceinline__ void cp_commit() {
    asm volatile("cp.async.commit_group;" ::: "memory");
}
__device__ __forceinline__ void cp_wait1() {
    asm volatile("cp.async.wait_group 1;" ::: "memory");
}
__device__ __forceinline__ uint32_t h2_bits(float lo, float hi) {
    __half2 h = __floats2half2_rn(lo, hi);
    return *(uint32_t*)&h;
}

// ================= kernel 0: W fp32 -> fp16 ([v][k] row-major) ==============
__global__ void __launch_bounds__(256)
wconv_kernel(const float* __restrict__ W) {
    int i = blockIdx.x * 256 + threadIdx.x;          // float4 id, 36864 total
    float4 x = ((const float4*)W)[i];
    ((uint2*)g_Wf16)[i] = make_uint2(h2_bits(x.x, x.y), h2_bits(x.z, x.w));
}

// ====== kernel 1: gather + fp16 HMMA GEMM + tanh + h + scores ===============
__global__ void __launch_bounds__(cfg::NTH, 1)
k1_mma_kernel(const int* __restrict__ starts,
              const int* __restrict__ paths,
              const int* __restrict__ ends,
              const float* __restrict__ node_emb,
              const float* __restrict__ path_emb,
              const float* __restrict__ avec) {
    using namespace cfg;
    extern __shared__ char smem[];
    const uint32_t sb = smem_u32(smem);
    const int tid = threadIdx.x;
    const int wid = tid >> 5, lane = tid & 31;
    const int wm = wid & 3;              // M slice (32 rows)
    const int wn = wid >> 2;             // N slice (64 cols of 128-chunk)
    const int tile = blockIdx.x;
    int* sidx = (int*)(smem + IDX);
    float* red = (float*)(smem + RED);

    // ---- indices ----
    if (tid < 128) {
        int r = tile * 128 + tid;
        sidx[tid]       = starts[r];
        sidx[128 + tid] = paths[r];
        sidx[256 + tid] = ends[r];
    }
    __syncthreads();

    // ---- B chunk staging: [128 n][32 k] fp16 = 512 x 16B ----
    auto stageB = [&](int q, uint32_t buf) {
        const int nt = q / 12, kc = q % 12;
        #pragma unroll
        for (int i = 0; i < 2; ++i) {
            int t = tid + i * 256;                   // 0..511
            int n = t >> 2, ch = t & 3;              // row, 16B chunk (8 fp16)
            const __half* src = g_Wf16 +
                ((size_t)(nt * 128 + n) * 384 + kc * 32 + ch * 8);
            cp_async16(sb + buf + (uint32_t)n * (BPAD * 2) + (uint32_t)ch * 16, src);
        }
        cp_commit();
    };
    stageB(0, B0);                                   // overlaps gather

    // ---- gather ctx rows -> fp16 into padded A ----
    #pragma unroll 2
    for (int i = 0; i < 48; ++i) {
        int task = tid + i * 256;                    // 0..12287
        int j = task & 31;                           // float4 within 128-elem row
        int rem = task >> 5;
        int seg = rem % 3, row = rem / 3;
        int idx = sidx[seg * 128 + row];
        const float4* src = (seg == 1) ? (const float4*)path_emb
                                       : (const float4*)node_emb;
        float4 x = __ldg(src + (size_t)idx * 32 + j);
        int k = seg * 128 + j * 4;
        *(uint2*)(smem + A_OFF + (uint32_t)row * (APAD * 2) + (uint32_t)k * 2) =
            make_uint2(h2_bits(x.x, x.y), h2_bits(x.z, x.w));
    }
    __syncthreads();
    stageB(1, B1);

    // ---- ldmatrix lane addresses (R3-proven b16 layout) ----
    const uint32_t a_lane = sb + A_OFF + (uint32_t)(wm * 32 + (lane & 15)) * (APAD * 2)
                          + (uint32_t)(lane >> 4) * 16;
    const int bgrp = lane >> 3;
    const uint32_t b_lane = (uint32_t)(((bgrp & 2) << 2) + (lane & 7)) * (BPAD * 2)
                          + (uint32_t)(bgrp & 1) * 16;

    float sc[2][2] = {{0.f, 0.f}, {0.f, 0.f}};       // score partials [mi][rowhalf]
    const size_t rowbase = (size_t)tile * 128;

    for (int nt = 0; nt < 3; ++nt) {
        float acc[2][8][4];
        #pragma unroll
        for (int mi = 0; mi < 2; ++mi)
            #pragma unroll
            for (int ni = 0; ni < 8; ++ni)
                #pragma unroll
                for (int q = 0; q < 4; ++q) acc[mi][ni][q] = 0.f;

        for (int kc = 0; kc < 12; ++kc) {
            const int q = nt * 12 + kc;
            const uint32_t buf = sb + ((q & 1) ? B1 : B0);
            // Group accounting: exactly one group is committed per loop
            // iteration (real stage or empty commit below), so at this wait
            // the outstanding set is {q, q+1-ish}; wait_group 1 leaves at most
            // the newest pending => chunk q's group is provably complete.
            // (R7 bug: at the tail, chunk 35's group WAS the newest and
            //  wait_group 1 returned without draining it -> read/copy race.)
            cp_wait1();
            __syncthreads();

            #pragma unroll
            for (int s = 0; s < 2; ++s) {            // two k16 steps
                const uint32_t akoff = (uint32_t)(kc * 32 + s * 16) * 2;
                uint32_t a[2][4];
                #pragma unroll
                for (int mi = 0; mi < 2; ++mi)
                    ldsm_x4(a[mi], a_lane + mi * (16 * APAD * 2) + akoff);
                #pragma unroll
                for (int bj = 0; bj < 4; ++bj) {
                    const uint32_t bn = (uint32_t)(wn * 64 + bj * 16) * (BPAD * 2)
                                      + (uint32_t)(s * 32);
                    uint32_t r[4];
                    ldsm_x4(r, buf + b_lane + bn);
                    #pragma unroll
                    for (int mi = 0; mi < 2; ++mi) {
                        mma_f16(acc[mi][2*bj],   a[mi], r[0], r[1]);
                        mma_f16(acc[mi][2*bj+1], a[mi], r[2], r[3]);
                    }
                }
            }

            __syncthreads();                         // reads of buf done
            if (q + 2 < NCHUNK) stageB(q + 2, (q & 1) ? B1 : B0);
            else                cp_commit();         // empty group: keeps the
                                                     // wait_group depth honest
        }

        // ---- epilogue: tanh, h store, score partials (overlaps staging) ----
        #pragma unroll
        for (int mi = 0; mi < 2; ++mi) {
            const int r0 = wm * 32 + mi * 16 + (lane >> 2);
            #pragma unroll
            for (int ni = 0; ni < 8; ++ni) {
                const int v0 = nt * 128 + wn * 64 + ni * 8 + (lane & 3) * 2;
                const float a0v = __ldg(avec + v0);
                const float a1v = __ldg(avec + v0 + 1);
                float h00 = tanhf(acc[mi][ni][0]);
                float h01 = tanhf(acc[mi][ni][1]);
                float h10 = tanhf(acc[mi][ni][2]);
                float h11 = tanhf(acc[mi][ni][3]);
                *(float2*)(g_h + (rowbase + r0) * 384 + v0)     = make_float2(h00, h01);
                *(float2*)(g_h + (rowbase + r0 + 8) * 384 + v0) = make_float2(h10, h11);
                sc[mi][0] += h00 * a0v + h01 * a1v;
                sc[mi][1] += h10 * a0v + h11 * a1v;
            }
        }
    }

    // ---- score reduction: quad shfl, then cross-warp over wn ----
    #pragma unroll
    for (int mi = 0; mi < 2; ++mi)
        #pragma unroll
        for (int j = 0; j < 2; ++j) {
            float s = sc[mi][j];
            s += __shfl_xor_sync(0xFFFFFFFFu, s, 1);
            s += __shfl_xor_sync(0xFFFFFFFFu, s, 2);
            sc[mi][j] = s;
        }
    __syncthreads();
    if (wn == 1 && (lane & 3) == 0) {
        #pragma unroll
        for (int mi = 0; mi < 2; ++mi)
            #pragma unroll
            for (int j = 0; j < 2; ++j)
                red[wm * 32 + mi * 16 + j * 8 + (lane >> 2)] = sc[mi][j];
    }
    __syncthreads();
    if (wn == 0 && (lane & 3) == 0) {
        #pragma unroll
        for (int mi = 0; mi < 2; ++mi)
            #pragma unroll
            for (int j = 0; j < 2; ++j) {
                int lr = wm * 32 + mi * 16 + j * 8 + (lane >> 2);
                g_scores[rowbase + lr] = sc[mi][j] + red[lr];
            }
    }
}

// ================= kernel 2: softmax over C + weighted sum ==================
__global__ void __launch_bounds__(cfg::CV)
k2_softmax_kernel(float* __restrict__ out) {
    using namespace cfg;
    const int b = blockIdx.x;
    const int tid = threadIdx.x;

    __shared__ float scs[C];
    __shared__ float attn[C];
    __shared__ float red[32];
    __shared__ float s_max, s_sum;

    if (tid < C) scs[tid] = g_scores[b * C + tid];
    __syncthreads();

    if (tid < 32) {
        float m = -3.4e38f;
        for (int c = tid; c < C; c += 32) m = fmaxf(m, scs[c]);
        red[tid] = m;
    }
    __syncthreads();
    if (tid == 0) {
        float m = red[0];
        #pragma unroll
        for (int j = 1; j < 32; ++j) m = fmaxf(m, red[j]);
        s_max = m;
    }
    __syncthreads();
    if (tid < 32) {
        float s = 0.f;
        for (int c = tid; c < C; c += 32) s += expf(scs[c] - s_max);
        red[tid] = s;
    }
    __syncthreads();
    if (tid == 0) {
        float s = 0.f;
        #pragma unroll
        for (int j = 0; j < 32; ++j) s += red[j];
        s_sum = s;
    }
    __syncthreads();
    if (tid < C) attn[tid] = expf(scs[tid] - s_max) / s_sum;
    __syncthreads();

    const float* hb = g_h + (size_t)b * C * CV;
    const int v = tid;
    float a0 = 0.f, a1 = 0.f, a2 = 0.f, a3 = 0.f;
    #pragma unroll 4
    for (int c = 0; c < C; c += 4) {
        a0 = fmaf(attn[c + 0], hb[(size_t)(c + 0) * CV + v], a0);
        a1 = fmaf(attn[c + 1], hb[(size_t)(c + 1) * CV + v], a1);
        a2 = fmaf(attn[c + 2], hb[(size_t)(c + 2) * CV + v], a2);
        a3 = fmaf(attn[c + 3], hb[(size_t)(c + 3) * CV + v], a3);
    }
    out[(size_t)b * CV + v] = (a0 + a1) + (a2 + a3);
}

// ================================ launch =====================================
extern "C" void kernel_launch(void* const* d_in, const int* in_sizes, int n_in,
                              void* d_out, int out_size) {
    (void)in_sizes; (void)n_in; (void)out_size;
    const int*   starts   = (const int*)d_in[0];
    const int*   paths    = (const int*)d_in[1];
    const int*   ends     = (const int*)d_in[2];
    /* masks d_in[3] unused by the reference */
    const float* node_emb = (const float*)d_in[4];
    const float* path_emb = (const float*)d_in[5];
    const float* W        = (const float*)d_in[6];
    const float* avec     = (const float*)d_in[7];
    float* out = (float*)d_out;

    cudaFuncSetAttribute(k1_mma_kernel,
                         cudaFuncAttributeMaxDynamicSharedMemorySize,
                         (int)cfg::SMEM_BYTES);

    wconv_kernel<<<cfg::CV * cfg::F / 4 / 256, 256>>>(W);
    k1_mma_kernel<<<cfg::NTILES, cfg::NTH, cfg::SMEM_BYTES>>>(
        starts, paths, ends, node_emb, path_emb, avec);
    k2_softmax_kernel<<<cfg::B, cfg::CV>>>(out);
}

// round 9
// speedup vs baseline: 3.5324x; 1.3436x over previous
#include <cuda_runtime.h>
#include <cuda_fp16.h>
#include <cstdint>
#include <cstddef>

// ============================ problem constants =============================
namespace cfg {
constexpr int B  = 512;
constexpr int C  = 200;
constexpr int E  = 128;
constexpr int CV = 384;
constexpr int F  = 384;                 // K dim (3E)
constexpr int ROWS = B * C;             // 102400
constexpr int NTILES = ROWS / 128;      // 800
constexpr int NTH = 512;                // 16 warps: 4 (M) x 4 (N)

constexpr int APAD = 392;               // A row: 384 + 8 fp16 -> 784 B
constexpr int BPAD = 40;                // B row: 32 + 8 fp16  -> 80 B

// dynamic smem layout (bytes)
constexpr uint32_t A_OFF = 0;            // [128][392] fp16 = 100352
constexpr uint32_t B0    = 100352;       // [128][40] fp16 = 10240
constexpr uint32_t B1    = 110592;       // 10240
constexpr uint32_t IDX   = 120832;       // 384 ints = 1536
constexpr uint32_t RED   = 122368;       // 3 x 128 floats = 1536
constexpr uint32_t SMEM_BYTES = 123904;
constexpr int NCHUNK = 36;               // 3 nt x 12 kc
}

// ===================== device scratch (no runtime alloc) ====================
__device__ __half    g_Wf16[cfg::CV * cfg::F];       // W fp16, [v][k] row-major
__device__ uint32_t  g_h2[(size_t)cfg::ROWS * cfg::CV / 2];  // h as half2 pairs
__device__ float     g_scores[cfg::ROWS];

// ============================== PTX helpers =================================
__device__ __forceinline__ uint32_t smem_u32(const void* p) {
    uint32_t a;
    asm("{ .reg .u64 t; cvta.to.shared.u64 t, %1; cvt.u32.u64 %0, t; }" : "=r"(a) : "l"(p));
    return a;
}
__device__ __forceinline__ void ldsm_x4(uint32_t (&r)[4], uint32_t addr) {
    asm volatile("ldmatrix.sync.aligned.m8n8.x4.shared.b16 {%0,%1,%2,%3}, [%4];"
                 : "=r"(r[0]), "=r"(r[1]), "=r"(r[2]), "=r"(r[3]) : "r"(addr));
}
__device__ __forceinline__ void mma_f16(float (&d)[4], const uint32_t (&a)[4],
                                        uint32_t b0, uint32_t b1) {
    asm volatile(
        "mma.sync.aligned.m16n8k16.row.col.f32.f16.f16.f32 "
        "{%0,%1,%2,%3}, {%4,%5,%6,%7}, {%8,%9}, {%0,%1,%2,%3};"
        : "+f"(d[0]), "+f"(d[1]), "+f"(d[2]), "+f"(d[3])
        : "r"(a[0]), "r"(a[1]), "r"(a[2]), "r"(a[3]), "r"(b0), "r"(b1));
}
__device__ __forceinline__ void cp_async16(uint32_t dst, const void* src) {
    asm volatile("cp.async.cg.shared.global [%0], [%1], 16;"
                 :: "r"(dst), "l"(src) : "memory");
}
__device__ __forceinline__ void cp_commit() {
    asm volatile("cp.async.commit_group;" ::: "memory");
}
__device__ __forceinline__ void cp_wait1() {
    asm volatile("cp.async.wait_group 1;" ::: "memory");
}
__device__ __forceinline__ uint32_t h2_bits(float lo, float hi) {
    __half2 h = __floats2half2_rn(lo, hi);
    return *(uint32_t*)&h;
}
// fast branchless tanh: 1 MUFU.EX2 + MUFU.RCP path, abs err ~1e-6
__device__ __forceinline__ float ftanh(float x) {
    x = fminf(fmaxf(x, -15.f), 15.f);
    float t = __expf(2.f * x);
    return __fdividef(t - 1.f, t + 1.f);
}

// ================= kernel 0: W fp32 -> fp16 ([v][k] row-major) ==============
__global__ void __launch_bounds__(256)
wconv_kernel(const float* __restrict__ W) {
    int i = blockIdx.x * 256 + threadIdx.x;          // float4 id, 36864 total
    float4 x = ((const float4*)W)[i];
    ((uint2*)g_Wf16)[i] = make_uint2(h2_bits(x.x, x.y), h2_bits(x.z, x.w));
}

// ====== kernel 1: gather + fp16 HMMA GEMM + tanh + h + scores ===============
__global__ void __launch_bounds__(cfg::NTH, 1)
k1_mma_kernel(const int* __restrict__ starts,
              const int* __restrict__ paths,
              const int* __restrict__ ends,
              const float* __restrict__ node_emb,
              const float* __restrict__ path_emb,
              const float* __restrict__ avec) {
    using namespace cfg;
    extern __shared__ char smem[];
    const uint32_t sb = smem_u32(smem);
    const int tid = threadIdx.x;
    const int wid = tid >> 5, lane = tid & 31;
    const int wm = wid & 3;              // M slice (32 rows)
    const int wn = wid >> 2;             // N slice (32 cols of 128-chunk)
    const int tile = blockIdx.x;
    int* sidx = (int*)(smem + IDX);
    float* red = (float*)(smem + RED);   // [3][128]

    // ---- indices ----
    if (tid < 128) {
        int r = tile * 128 + tid;
        sidx[tid]       = starts[r];
        sidx[128 + tid] = paths[r];
        sidx[256 + tid] = ends[r];
    }
    __syncthreads();

    // ---- B chunk staging: [128 n][32 k] fp16 = 512 x 16B, 1 per thread ----
    auto stageB = [&](int q, uint32_t buf) {
        const int nt = q / 12, kc = q % 12;
        int n = tid >> 2, ch = tid & 3;              // row, 16B chunk (8 fp16)
        const __half* src = g_Wf16 +
            ((size_t)(nt * 128 + n) * 384 + kc * 32 + ch * 8);
        cp_async16(sb + buf + (uint32_t)n * (BPAD * 2) + (uint32_t)ch * 16, src);
        cp_commit();
    };
    stageB(0, B0);                                   // overlaps gather

    // ---- gather ctx rows -> fp16 into padded A (per-seg loops: no div/mod) --
    #pragma unroll
    for (int seg = 0; seg < 3; ++seg) {
        const float4* src = (seg == 1) ? (const float4*)path_emb
                                       : (const float4*)node_emb;
        #pragma unroll 2
        for (int i = 0; i < 8; ++i) {
            int task = tid + i * 512;                // 0..4095
            int row = task >> 5, j = task & 31;
            int idx = sidx[seg * 128 + row];
            float4 x = __ldg(src + (size_t)idx * 32 + j);
            int k = seg * 128 + j * 4;
            *(uint2*)(smem + A_OFF + (uint32_t)row * (APAD * 2) + (uint32_t)k * 2) =
                make_uint2(h2_bits(x.x, x.y), h2_bits(x.z, x.w));
        }
    }
    __syncthreads();
    stageB(1, B1);

    // ---- ldmatrix lane addresses ----
    const uint32_t a_lane = sb + A_OFF + (uint32_t)(wm * 32 + (lane & 15)) * (APAD * 2)
                          + (uint32_t)(lane >> 4) * 16;
    const int bgrp = lane >> 3;
    const uint32_t b_lane = (uint32_t)(((bgrp & 2) << 2) + (lane & 7)) * (BPAD * 2)
                          + (uint32_t)(bgrp & 1) * 16;

    float sc[2][2] = {{0.f, 0.f}, {0.f, 0.f}};       // score partials [mi][rowhalf]
    const size_t rowbase = (size_t)tile * 128;

    for (int nt = 0; nt < 3; ++nt) {
        float acc[2][4][4];
        #pragma unroll
        for (int mi = 0; mi < 2; ++mi)
            #pragma unroll
            for (int ni = 0; ni < 4; ++ni)
                #pragma unroll
                for (int q = 0; q < 4; ++q) acc[mi][ni][q] = 0.f;

        for (int kc = 0; kc < 12; ++kc) {
            const int q = nt * 12 + kc;
            const uint32_t buf = sb + ((q & 1) ? B1 : B0);
            // One group committed per iteration (real stage or empty commit),
            // so wait_group 1 provably drains chunk q's group (R8 tail fix).
            cp_wait1();
            __syncthreads();

            #pragma unroll
            for (int s = 0; s < 2; ++s) {            // two k16 steps
                const uint32_t akoff = (uint32_t)(kc * 32 + s * 16) * 2;
                uint32_t a[2][4];
                #pragma unroll
                for (int mi = 0; mi < 2; ++mi)
                    ldsm_x4(a[mi], a_lane + mi * (16 * APAD * 2) + akoff);
                #pragma unroll
                for (int bj = 0; bj < 2; ++bj) {
                    const uint32_t bn = (uint32_t)(wn * 32 + bj * 16) * (BPAD * 2)
                                      + (uint32_t)(s * 32);
                    uint32_t r[4];
                    ldsm_x4(r, buf + b_lane + bn);
                    #pragma unroll
                    for (int mi = 0; mi < 2; ++mi) {
                        mma_f16(acc[mi][2*bj],   a[mi], r[0], r[1]);
                        mma_f16(acc[mi][2*bj+1], a[mi], r[2], r[3]);
                    }
                }
            }

            __syncthreads();                         // reads of buf done
            if (q + 2 < NCHUNK) stageB(q + 2, (q & 1) ? B1 : B0);
            else                cp_commit();         // empty group, keep depth
        }

        // ---- epilogue: fast tanh, half2 h store, score partials ----
        #pragma unroll
        for (int mi = 0; mi < 2; ++mi) {
            const int r0 = wm * 32 + mi * 16 + (lane >> 2);
            #pragma unroll
            for (int ni = 0; ni < 4; ++ni) {
                const int v0 = nt * 128 + wn * 32 + ni * 8 + (lane & 3) * 2;
                const float a0v = __ldg(avec + v0);
                const float a1v = __ldg(avec + v0 + 1);
                float h00 = ftanh(acc[mi][ni][0]);
                float h01 = ftanh(acc[mi][ni][1]);
                float h10 = ftanh(acc[mi][ni][2]);
                float h11 = ftanh(acc[mi][ni][3]);
                g_h2[(rowbase + r0) * 192 + (v0 >> 1)]     = h2_bits(h00, h01);
                g_h2[(rowbase + r0 + 8) * 192 + (v0 >> 1)] = h2_bits(h10, h11);
                sc[mi][0] += h00 * a0v + h01 * a1v;
                sc[mi][1] += h10 * a0v + h11 * a1v;
            }
        }
    }

    // ---- score reduction: quad shfl, then cross-warp over wn=0..3 ----
    #pragma unroll
    for (int mi = 0; mi < 2; ++mi)
        #pragma unroll
        for (int j = 0; j < 2; ++j) {
            float s = sc[mi][j];
            s += __shfl_xor_sync(0xFFFFFFFFu, s, 1);
            s += __shfl_xor_sync(0xFFFFFFFFu, s, 2);
            sc[mi][j] = s;
        }
    __syncthreads();
    if (wn > 0 && (lane & 3) == 0) {
        #pragma unroll
        for (int mi = 0; mi < 2; ++mi)
            #pragma unroll
            for (int j = 0; j < 2; ++j)
                red[(wn - 1) * 128 + wm * 32 + mi * 16 + j * 8 + (lane >> 2)] =
                    sc[mi][j];
    }
    __syncthreads();
    if (wn == 0 && (lane & 3) == 0) {
        #pragma unroll
        for (int mi = 0; mi < 2; ++mi)
            #pragma unroll
            for (int j = 0; j < 2; ++j) {
                int lr = wm * 32 + mi * 16 + j * 8 + (lane >> 2);
                // fixed summation order: deterministic
                g_scores[rowbase + lr] =
                    sc[mi][j] + red[lr] + red[128 + lr] + red[256 + lr];
            }
    }
}

// ================= kernel 2: softmax over C + weighted sum ==================
__global__ void __launch_bounds__(cfg::CV)
k2_softmax_kernel(float* __restrict__ out) {
    using namespace cfg;
    const int b = blockIdx.x;
    const int tid = threadIdx.x;

    __shared__ float scs[C];
    __shared__ float attn[C];
    __shared__ float red[32];
    __shared__ float s_max, s_sum;

    if (tid < C) scs[tid] = g_scores[b * C + tid];
    __syncthreads();

    if (tid < 32) {
        float m = -3.4e38f;
        for (int c = tid; c < C; c += 32) m = fmaxf(m, scs[c]);
        red[tid] = m;
    }
    __syncthreads();
    if (tid == 0) {
        float m = red[0];
        #pragma unroll
        for (int j = 1; j < 32; ++j) m = fmaxf(m, red[j]);
        s_max = m;
    }
    __syncthreads();
    if (tid < 32) {
        float s = 0.f;
        for (int c = tid; c < C; c += 32) s += expf(scs[c] - s_max);
        red[tid] = s;
    }
    __syncthreads();
    if (tid == 0) {
        float s = 0.f;
        #pragma unroll
        for (int j = 0; j < 32; ++j) s += red[j];
        s_sum = s;
    }
    __syncthreads();
    if (tid < C) attn[tid] = expf(scs[tid] - s_max) / s_sum;
    __syncthreads();

    // h stored as half; read per-v halves (coalesced 768B rows)
    const __half* hb = (const __half*)g_h2 + (size_t)b * C * CV;
    const int v = tid;
    float a0 = 0.f, a1 = 0.f, a2 = 0.f, a3 = 0.f;
    #pragma unroll 4
    for (int c = 0; c < C; c += 4) {
        a0 = fmaf(attn[c + 0], __half2float(hb[(size_t)(c + 0) * CV + v]), a0);
        a1 = fmaf(attn[c + 1], __half2float(hb[(size_t)(c + 1) * CV + v]), a1);
        a2 = fmaf(attn[c + 2], __half2float(hb[(size_t)(c + 2) * CV + v]), a2);
        a3 = fmaf(attn[c + 3], __half2float(hb[(size_t)(c + 3) * CV + v]), a3);
    }
    out[(size_t)b * CV + v] = (a0 + a1) + (a2 + a3);
}

// ================================ launch =====================================
extern "C" void kernel_launch(void* const* d_in, const int* in_sizes, int n_in,
                              void* d_out, int out_size) {
    (void)in_sizes; (void)n_in; (void)out_size;
    const int*   starts   = (const int*)d_in[0];
    const int*   paths    = (const int*)d_in[1];
    const int*   ends     = (const int*)d_in[2];
    /* masks d_in[3] unused by the reference */
    const float* node_emb = (const float*)d_in[4];
    const float* path_emb = (const float*)d_in[5];
    const float* W        = (const float*)d_in[6];
    const float* avec     = (const float*)d_in[7];
    float* out = (float*)d_out;

    cudaFuncSetAttribute(k1_mma_kernel,
                         cudaFuncAttributeMaxDynamicSharedMemorySize,
                         (int)cfg::SMEM_BYTES);

    wconv_kernel<<<cfg::CV * cfg::F / 4 / 256, 256>>>(W);
    k1_mma_kernel<<<cfg::NTILES, cfg::NTH, cfg::SMEM_BYTES>>>(
        starts, paths, ends, node_emb, path_emb, avec);
    k2_softmax_kernel<<<cfg::B, cfg::CV>>>(out);
}

// round 10
// speedup vs baseline: 4.0436x; 1.1447x over previous
#include <cuda_runtime.h>
#include <cuda_fp16.h>
#include <cstdint>
#include <cstddef>

// ============================ problem constants =============================
namespace cfg {
constexpr int B  = 512;
constexpr int C  = 200;
constexpr int E  = 128;
constexpr int CV = 384;
constexpr int F  = 384;                 // K dim (3E)
constexpr int ROWS = B * C;             // 102400
constexpr int MT = 64;                  // rows per CTA tile
constexpr int NTILES = ROWS / MT;       // 1600
constexpr int NTH = 256;                // 8 warps: 2 (M) x 4 (N)

constexpr int APAD = 392;               // A row: 384 + 8 fp16 -> 784 B
constexpr int BPAD = 40;                // B row: 32 + 8 fp16  -> 80 B

// dynamic smem layout (bytes)
constexpr uint32_t A_OFF = 0;            // [64][392] fp16 = 50176
constexpr uint32_t B0    = 50176;        // [128][40] fp16 = 10240
constexpr uint32_t B1    = 60416;        // 10240
constexpr uint32_t IDX   = 70656;        // 192 ints = 768
constexpr uint32_t RED   = 71424;        // 3 x 64 floats = 768
constexpr uint32_t SMEM_BYTES = 72192;   // x2 CTAs = 144384 < 227KB cap
constexpr int NCHUNK = 36;               // 3 nt x 12 kc
}

// ===================== device scratch (no runtime alloc) ====================
__device__ __half    g_Wf16[cfg::CV * cfg::F];       // W fp16, [v][k] row-major
__device__ uint32_t  g_h2[(size_t)cfg::ROWS * cfg::CV / 2];  // h as half2 pairs
__device__ float     g_scores[cfg::ROWS];

// ============================== PTX helpers =================================
__device__ __forceinline__ uint32_t smem_u32(const void* p) {
    uint32_t a;
    asm("{ .reg .u64 t; cvta.to.shared.u64 t, %1; cvt.u32.u64 %0, t; }" : "=r"(a) : "l"(p));
    return a;
}
__device__ __forceinline__ void ldsm_x4(uint32_t (&r)[4], uint32_t addr) {
    asm volatile("ldmatrix.sync.aligned.m8n8.x4.shared.b16 {%0,%1,%2,%3}, [%4];"
                 : "=r"(r[0]), "=r"(r[1]), "=r"(r[2]), "=r"(r[3]) : "r"(addr));
}
__device__ __forceinline__ void mma_f16(float (&d)[4], const uint32_t (&a)[4],
                                        uint32_t b0, uint32_t b1) {
    asm volatile(
        "mma.sync.aligned.m16n8k16.row.col.f32.f16.f16.f32 "
        "{%0,%1,%2,%3}, {%4,%5,%6,%7}, {%8,%9}, {%0,%1,%2,%3};"
        : "+f"(d[0]), "+f"(d[1]), "+f"(d[2]), "+f"(d[3])
        : "r"(a[0]), "r"(a[1]), "r"(a[2]), "r"(a[3]), "r"(b0), "r"(b1));
}
__device__ __forceinline__ void cp_async16(uint32_t dst, const void* src) {
    asm volatile("cp.async.cg.shared.global [%0], [%1], 16;"
                 :: "r"(dst), "l"(src) : "memory");
}
__device__ __forceinline__ void cp_commit() {
    asm volatile("cp.async.commit_group;" ::: "memory");
}
__device__ __forceinline__ void cp_wait1() {
    asm volatile("cp.async.wait_group 1;" ::: "memory");
}
__device__ __forceinline__ uint32_t h2_bits(float lo, float hi) {
    __half2 h = __floats2half2_rn(lo, hi);
    return *(uint32_t*)&h;
}
// fast branchless tanh: MUFU.EX2 + fast divide, abs err ~1e-6
__device__ __forceinline__ float ftanh(float x) {
    x = fminf(fmaxf(x, -15.f), 15.f);
    float t = __expf(2.f * x);
    return __fdividef(t - 1.f, t + 1.f);
}

// ================= kernel 0: W fp32 -> fp16 ([v][k] row-major) ==============
__global__ void __launch_bounds__(256)
wconv_kernel(const float* __restrict__ W) {
    int i = blockIdx.x * 256 + threadIdx.x;          // float4 id, 36864 total
    float4 x = ((const float4*)W)[i];
    ((uint2*)g_Wf16)[i] = make_uint2(h2_bits(x.x, x.y), h2_bits(x.z, x.w));
}

// ====== kernel 1: gather + fp16 HMMA GEMM + tanh + h + scores ===============
__global__ void __launch_bounds__(cfg::NTH, 2)
k1_mma_kernel(const int* __restrict__ starts,
              const int* __restrict__ paths,
              const int* __restrict__ ends,
              const float* __restrict__ node_emb,
              const float* __restrict__ path_emb,
              const float* __restrict__ avec) {
    using namespace cfg;
    extern __shared__ char smem[];
    const uint32_t sb = smem_u32(smem);
    const int tid = threadIdx.x;
    const int wid = tid >> 5, lane = tid & 31;
    const int wm = wid & 1;              // M slice (32 rows)
    const int wn = wid >> 1;             // N slice (32 cols of 128-chunk)
    const int tile = blockIdx.x;
    int* sidx = (int*)(smem + IDX);
    float* red = (float*)(smem + RED);   // [3][64]

    // ---- indices (64 rows x 3) ----
    if (tid < 192) {
        int seg = tid >> 6, r = tid & 63;
        const int* p = (seg == 0) ? starts : (seg == 1) ? paths : ends;
        sidx[tid] = p[tile * 64 + r];
    }
    __syncthreads();

    // ---- B chunk staging: [128 n][32 k] fp16 = 512 x 16B, 2 per thread ----
    auto stageB = [&](int q, uint32_t buf) {
        const int nt = q / 12, kc = q % 12;
        #pragma unroll
        for (int i = 0; i < 2; ++i) {
            int t = tid + i * 256;                   // 0..511
            int n = t >> 2, ch = t & 3;              // row, 16B chunk (8 fp16)
            const __half* src = g_Wf16 +
                ((size_t)(nt * 128 + n) * 384 + kc * 32 + ch * 8);
            cp_async16(sb + buf + (uint32_t)n * (BPAD * 2) + (uint32_t)ch * 16, src);
        }
        cp_commit();
    };
    stageB(0, B0);                                   // overlaps gather

    // ---- gather ctx rows -> fp16 into padded A (per-seg: no div/mod) ----
    #pragma unroll
    for (int seg = 0; seg < 3; ++seg) {
        const float4* src = (seg == 1) ? (const float4*)path_emb
                                       : (const float4*)node_emb;
        #pragma unroll 2
        for (int i = 0; i < 8; ++i) {
            int task = tid + i * 256;                // 0..2047
            int row = task >> 5, j = task & 31;
            int idx = sidx[seg * 64 + row];
            float4 x = __ldg(src + (size_t)idx * 32 + j);
            int k = seg * 128 + j * 4;
            *(uint2*)(smem + A_OFF + (uint32_t)row * (APAD * 2) + (uint32_t)k * 2) =
                make_uint2(h2_bits(x.x, x.y), h2_bits(x.z, x.w));
        }
    }
    __syncthreads();
    stageB(1, B1);

    // ---- ldmatrix lane addresses ----
    const uint32_t a_lane = sb + A_OFF + (uint32_t)(wm * 32 + (lane & 15)) * (APAD * 2)
                          + (uint32_t)(lane >> 4) * 16;
    const int bgrp = lane >> 3;
    const uint32_t b_lane = (uint32_t)(((bgrp & 2) << 2) + (lane & 7)) * (BPAD * 2)
                          + (uint32_t)(bgrp & 1) * 16;

    float sc[2][2] = {{0.f, 0.f}, {0.f, 0.f}};       // score partials [mi][rowhalf]
    const size_t rowbase = (size_t)tile * 64;

    for (int nt = 0; nt < 3; ++nt) {
        float acc[2][4][4];
        #pragma unroll
        for (int mi = 0; mi < 2; ++mi)
            #pragma unroll
            for (int ni = 0; ni < 4; ++ni)
                #pragma unroll
                for (int q = 0; q < 4; ++q) acc[mi][ni][q] = 0.f;

        for (int kc = 0; kc < 12; ++kc) {
            const int q = nt * 12 + kc;
            const uint32_t buf = sb + ((q & 1) ? B1 : B0);
            // One group committed per iteration (real stage or empty commit),
            // so wait_group 1 provably drains chunk q's group (R8 tail fix).
            cp_wait1();
            __syncthreads();

            #pragma unroll
            for (int s = 0; s < 2; ++s) {            // two k16 steps
                const uint32_t akoff = (uint32_t)(kc * 32 + s * 16) * 2;
                uint32_t a[2][4];
                #pragma unroll
                for (int mi = 0; mi < 2; ++mi)
                    ldsm_x4(a[mi], a_lane + mi * (16 * APAD * 2) + akoff);
                #pragma unroll
                for (int bj = 0; bj < 2; ++bj) {
                    const uint32_t bn = (uint32_t)(wn * 32 + bj * 16) * (BPAD * 2)
                                      + (uint32_t)(s * 32);
                    uint32_t r[4];
                    ldsm_x4(r, buf + b_lane + bn);
                    #pragma unroll
                    for (int mi = 0; mi < 2; ++mi) {
                        mma_f16(acc[mi][2*bj],   a[mi], r[0], r[1]);
                        mma_f16(acc[mi][2*bj+1], a[mi], r[2], r[3]);
                    }
                }
            }

            __syncthreads();                         // reads of buf done
            if (q + 2 < NCHUNK) stageB(q + 2, (q & 1) ? B1 : B0);
            else                cp_commit();         // empty group, keep depth
        }

        // ---- epilogue: fast tanh, half2 h store, score partials ----
        #pragma unroll
        for (int mi = 0; mi < 2; ++mi) {
            const int r0 = wm * 32 + mi * 16 + (lane >> 2);
            #pragma unroll
            for (int ni = 0; ni < 4; ++ni) {
                const int v0 = nt * 128 + wn * 32 + ni * 8 + (lane & 3) * 2;
                const float a0v = __ldg(avec + v0);
                const float a1v = __ldg(avec + v0 + 1);
                float h00 = ftanh(acc[mi][ni][0]);
                float h01 = ftanh(acc[mi][ni][1]);
                float h10 = ftanh(acc[mi][ni][2]);
                float h11 = ftanh(acc[mi][ni][3]);
                g_h2[(rowbase + r0) * 192 + (v0 >> 1)]     = h2_bits(h00, h01);
                g_h2[(rowbase + r0 + 8) * 192 + (v0 >> 1)] = h2_bits(h10, h11);
                sc[mi][0] += h00 * a0v + h01 * a1v;
                sc[mi][1] += h10 * a0v + h11 * a1v;
            }
        }
    }

    // ---- score reduction: quad shfl, then cross-warp over wn=0..3 ----
    #pragma unroll
    for (int mi = 0; mi < 2; ++mi)
        #pragma unroll
        for (int j = 0; j < 2; ++j) {
            float s = sc[mi][j];
            s += __shfl_xor_sync(0xFFFFFFFFu, s, 1);
            s += __shfl_xor_sync(0xFFFFFFFFu, s, 2);
            sc[mi][j] = s;
        }
    __syncthreads();
    if (wn > 0 && (lane & 3) == 0) {
        #pragma unroll
        for (int mi = 0; mi < 2; ++mi)
            #pragma unroll
            for (int j = 0; j < 2; ++j)
                red[(wn - 1) * 64 + wm * 32 + mi * 16 + j * 8 + (lane >> 2)] =
                    sc[mi][j];
    }
    __syncthreads();
    if (wn == 0 && (lane & 3) == 0) {
        #pragma unroll
        for (int mi = 0; mi < 2; ++mi)
            #pragma unroll
            for (int j = 0; j < 2; ++j) {
                int lr = wm * 32 + mi * 16 + j * 8 + (lane >> 2);
                // fixed summation order: deterministic
                g_scores[rowbase + lr] =
                    sc[mi][j] + red[lr] + red[64 + lr] + red[128 + lr];
            }
    }
}

// ================= kernel 2: softmax over C + weighted sum ==================
__global__ void __launch_bounds__(cfg::CV)
k2_softmax_kernel(float* __restrict__ out) {
    using namespace cfg;
    const int b = blockIdx.x;
    const int tid = threadIdx.x;

    __shared__ float scs[C];
    __shared__ float attn[C];
    __shared__ float red[32];
    __shared__ float s_max, s_sum;

    if (tid < C) scs[tid] = g_scores[b * C + tid];
    __syncthreads();

    if (tid < 32) {
        float m = -3.4e38f;
        for (int c = tid; c < C; c += 32) m = fmaxf(m, scs[c]);
        red[tid] = m;
    }
    __syncthreads();
    if (tid == 0) {
        float m = red[0];
        #pragma unroll
        for (int j = 1; j < 32; ++j) m = fmaxf(m, red[j]);
        s_max = m;
    }
    __syncthreads();
    if (tid < 32) {
        float s = 0.f;
        for (int c = tid; c < C; c += 32) s += expf(scs[c] - s_max);
        red[tid] = s;
    }
    __syncthreads();
    if (tid == 0) {
        float s = 0.f;
        #pragma unroll
        for (int j = 0; j < 32; ++j) s += red[j];
        s_sum = s;
    }
    __syncthreads();
    if (tid < C) attn[tid] = expf(scs[tid] - s_max) / s_sum;
    __syncthreads();

    // h stored as half; read per-v halves (coalesced 768B rows)
    const __half* hb = (const __half*)g_h2 + (size_t)b * C * CV;
    const int v = tid;
    float a0 = 0.f, a1 = 0.f, a2 = 0.f, a3 = 0.f;
    #pragma unroll 4
    for (int c = 0; c < C; c += 4) {
        a0 = fmaf(attn[c + 0], __half2float(hb[(size_t)(c + 0) * CV + v]), a0);
        a1 = fmaf(attn[c + 1], __half2float(hb[(size_t)(c + 1) * CV + v]), a1);
        a2 = fmaf(attn[c + 2], __half2float(hb[(size_t)(c + 2) * CV + v]), a2);
        a3 = fmaf(attn[c + 3], __half2float(hb[(size_t)(c + 3) * CV + v]), a3);
    }
    out[(size_t)b * CV + v] = (a0 + a1) + (a2 + a3);
}

// ================================ launch =====================================
extern "C" void kernel_launch(void* const* d_in, const int* in_sizes, int n_in,
                              void* d_out, int out_size) {
    (void)in_sizes; (void)n_in; (void)out_size;
    const int*   starts   = (const int*)d_in[0];
    const int*   paths    = (const int*)d_in[1];
    const int*   ends     = (const int*)d_in[2];
    /* masks d_in[3] unused by the reference */
    const float* node_emb = (const float*)d_in[4];
    const float* path_emb = (const float*)d_in[5];
    const float* W        = (const float*)d_in[6];
    const float* avec     = (const float*)d_in[7];
    float* out = (float*)d_out;

    cudaFuncSetAttribute(k1_mma_kernel,
                         cudaFuncAttributeMaxDynamicSharedMemorySize,
                         (int)cfg::SMEM_BYTES);

    wconv_kernel<<<cfg::CV * cfg::F / 4 / 256, 256>>>(W);
    k1_mma_kernel<<<cfg::NTILES, cfg::NTH, cfg::SMEM_BYTES>>>(
        starts, paths, ends, node_emb, path_emb, avec);
    k2_softmax_kernel<<<cfg::B, cfg::CV>>>(out);
}

// round 11
// speedup vs baseline: 4.8438x; 1.1979x over previous
#include <cuda_runtime.h>
#include <cuda_fp16.h>
#include <cstdint>
#include <cstddef>

// ============================ problem constants =============================
namespace cfg {
constexpr int B  = 512;
constexpr int C  = 200;
constexpr int E  = 128;
constexpr int CV = 384;
constexpr int F  = 384;                 // K dim (3E)
constexpr int ROWS = B * C;             // 102400
constexpr int MT = 64;                  // rows per CTA tile
constexpr int NTILES = ROWS / MT;       // 1600
constexpr int NTH = 256;                // 8 warps: 2 (M) x 4 (N)

constexpr int APAD = 392;               // A row: 384 + 8 fp16 -> 784 B
constexpr int BPAD = 40;                // B row: 32 + 8 fp16  -> 80 B

// dynamic smem layout (bytes)
constexpr uint32_t A_OFF = 0;            // [64][392] fp16 = 50176
constexpr uint32_t B0    = 50176;        // [128][40] fp16 = 10240
constexpr uint32_t B1    = 60416;        // 10240
constexpr uint32_t IDX   = 70656;        // 192 ints = 768
constexpr uint32_t RED   = 71424;        // 3 x 64 floats = 768
constexpr uint32_t SMEM_BYTES = 72192;   // x3 CTAs = 216576 <= 227KB SM budget
constexpr int NCHUNK = 36;               // 3 nt x 12 kc
}

// ===================== device scratch (no runtime alloc) ====================
__device__ __half    g_Wf16[cfg::CV * cfg::F];       // W fp16, [v][k] row-major
__device__ uint32_t  g_h2[(size_t)cfg::ROWS * cfg::CV / 2];  // h as half2 pairs
__device__ float     g_scores[cfg::ROWS];

// ============================== PTX helpers =================================
__device__ __forceinline__ uint32_t smem_u32(const void* p) {
    uint32_t a;
    asm("{ .reg .u64 t; cvta.to.shared.u64 t, %1; cvt.u32.u64 %0, t; }" : "=r"(a) : "l"(p));
    return a;
}
__device__ __forceinline__ void ldsm_x4(uint32_t (&r)[4], uint32_t addr) {
    asm volatile("ldmatrix.sync.aligned.m8n8.x4.shared.b16 {%0,%1,%2,%3}, [%4];"
                 : "=r"(r[0]), "=r"(r[1]), "=r"(r[2]), "=r"(r[3]) : "r"(addr));
}
__device__ __forceinline__ void mma_f16(float (&d)[4], const uint32_t (&a)[4],
                                        uint32_t b0, uint32_t b1) {
    asm volatile(
        "mma.sync.aligned.m16n8k16.row.col.f32.f16.f16.f32 "
        "{%0,%1,%2,%3}, {%4,%5,%6,%7}, {%8,%9}, {%0,%1,%2,%3};"
        : "+f"(d[0]), "+f"(d[1]), "+f"(d[2]), "+f"(d[3])
        : "r"(a[0]), "r"(a[1]), "r"(a[2]), "r"(a[3]), "r"(b0), "r"(b1));
}
__device__ __forceinline__ void cp_async16(uint32_t dst, const void* src) {
    asm volatile("cp.async.cg.shared.global [%0], [%1], 16;"
                 :: "r"(dst), "l"(src) : "memory");
}
__device__ __forceinline__ void cp_commit() {
    asm volatile("cp.async.commit_group;" ::: "memory");
}
__device__ __forceinline__ void cp_wait1() {
    asm volatile("cp.async.wait_group 1;" ::: "memory");
}
__device__ __forceinline__ uint32_t h2_bits(float lo, float hi) {
    __half2 h = __floats2half2_rn(lo, hi);
    return *(uint32_t*)&h;
}
// fast branchless tanh: MUFU.EX2 + fast divide, abs err ~1e-6
__device__ __forceinline__ float ftanh(float x) {
    x = fminf(fmaxf(x, -15.f), 15.f);
    float t = __expf(2.f * x);
    return __fdividef(t - 1.f, t + 1.f);
}

// ================= kernel 0: W fp32 -> fp16 ([v][k] row-major) ==============
__global__ void __launch_bounds__(256)
wconv_kernel(const float* __restrict__ W) {
    int i = blockIdx.x * 256 + threadIdx.x;          // float4 id, 36864 total
    float4 x = ((const float4*)W)[i];
    ((uint2*)g_Wf16)[i] = make_uint2(h2_bits(x.x, x.y), h2_bits(x.z, x.w));
}

// ====== kernel 1: gather + fp16 HMMA GEMM + tanh + h + scores ===============
__global__ void __launch_bounds__(cfg::NTH, 3)
k1_mma_kernel(const int* __restrict__ starts,
              const int* __restrict__ paths,
              const int* __restrict__ ends,
              const float* __restrict__ node_emb,
              const float* __restrict__ path_emb,
              const float* __restrict__ avec) {
    using namespace cfg;
    extern __shared__ char smem[];
    const uint32_t sb = smem_u32(smem);
    const int tid = threadIdx.x;
    const int wid = tid >> 5, lane = tid & 31;
    const int wm = wid & 1;              // M slice (32 rows)
    const int wn = wid >> 1;             // N slice (32 cols of 128-chunk)
    const int tile = blockIdx.x;
    int* sidx = (int*)(smem + IDX);
    float* red = (float*)(smem + RED);   // [3][64]

    // ---- indices (64 rows x 3) ----
    if (tid < 192) {
        int seg = tid >> 6, r = tid & 63;
        const int* p = (seg == 0) ? starts : (seg == 1) ? paths : ends;
        sidx[tid] = p[tile * 64 + r];
    }
    __syncthreads();

    // ---- B chunk staging: [128 n][32 k] fp16 = 512 x 16B, 2 per thread ----
    auto stageB = [&](int q, uint32_t buf) {
        const int nt = q / 12, kc = q % 12;
        #pragma unroll
        for (int i = 0; i < 2; ++i) {
            int t = tid + i * 256;                   // 0..511
            int n = t >> 2, ch = t & 3;              // row, 16B chunk (8 fp16)
            const __half* src = g_Wf16 +
                ((size_t)(nt * 128 + n) * 384 + kc * 32 + ch * 8);
            cp_async16(sb + buf + (uint32_t)n * (BPAD * 2) + (uint32_t)ch * 16, src);
        }
        cp_commit();
    };
    stageB(0, B0);                                   // overlaps gather

    // ---- gather ctx rows -> fp16 into padded A (per-seg: no div/mod) ----
    #pragma unroll
    for (int seg = 0; seg < 3; ++seg) {
        const float4* src = (seg == 1) ? (const float4*)path_emb
                                       : (const float4*)node_emb;
        #pragma unroll 2
        for (int i = 0; i < 8; ++i) {
            int task = tid + i * 256;                // 0..2047
            int row = task >> 5, j = task & 31;
            int idx = sidx[seg * 64 + row];
            float4 x = __ldg(src + (size_t)idx * 32 + j);
            int k = seg * 128 + j * 4;
            *(uint2*)(smem + A_OFF + (uint32_t)row * (APAD * 2) + (uint32_t)k * 2) =
                make_uint2(h2_bits(x.x, x.y), h2_bits(x.z, x.w));
        }
    }
    __syncthreads();
    stageB(1, B1);

    // ---- ldmatrix lane addresses ----
    const uint32_t a_lane = sb + A_OFF + (uint32_t)(wm * 32 + (lane & 15)) * (APAD * 2)
                          + (uint32_t)(lane >> 4) * 16;
    const int bgrp = lane >> 3;
    const uint32_t b_lane = (uint32_t)(((bgrp & 2) << 2) + (lane & 7)) * (BPAD * 2)
                          + (uint32_t)(bgrp & 1) * 16;

    float sc[2][2] = {{0.f, 0.f}, {0.f, 0.f}};       // score partials [mi][rowhalf]
    const size_t rowbase = (size_t)tile * 64;

    for (int nt = 0; nt < 3; ++nt) {
        float acc[2][4][4];
        #pragma unroll
        for (int mi = 0; mi < 2; ++mi)
            #pragma unroll
            for (int ni = 0; ni < 4; ++ni)
                #pragma unroll
                for (int q = 0; q < 4; ++q) acc[mi][ni][q] = 0.f;

        for (int kc = 0; kc < 12; ++kc) {
            const int q = nt * 12 + kc;
            const uint32_t buf = sb + ((q & 1) ? B1 : B0);
            // One group committed per iteration (real stage or empty commit),
            // so wait_group 1 provably drains chunk q's group (R8 tail fix).
            cp_wait1();
            __syncthreads();

            #pragma unroll
            for (int s = 0; s < 2; ++s) {            // two k16 steps
                const uint32_t akoff = (uint32_t)(kc * 32 + s * 16) * 2;
                uint32_t a[2][4];
                #pragma unroll
                for (int mi = 0; mi < 2; ++mi)
                    ldsm_x4(a[mi], a_lane + mi * (16 * APAD * 2) + akoff);
                #pragma unroll
                for (int bj = 0; bj < 2; ++bj) {
                    const uint32_t bn = (uint32_t)(wn * 32 + bj * 16) * (BPAD * 2)
                                      + (uint32_t)(s * 32);
                    uint32_t r[4];
                    ldsm_x4(r, buf + b_lane + bn);
                    #pragma unroll
                    for (int mi = 0; mi < 2; ++mi) {
                        mma_f16(acc[mi][2*bj],   a[mi], r[0], r[1]);
                        mma_f16(acc[mi][2*bj+1], a[mi], r[2], r[3]);
                    }
                }
            }

            __syncthreads();                         // reads of buf done
            if (q + 2 < NCHUNK) stageB(q + 2, (q & 1) ? B1 : B0);
            else                cp_commit();         // empty group, keep depth
        }

        // ---- epilogue: fast tanh, half2 h store, score partials ----
        #pragma unroll
        for (int mi = 0; mi < 2; ++mi) {
            const int r0 = wm * 32 + mi * 16 + (lane >> 2);
            #pragma unroll
            for (int ni = 0; ni < 4; ++ni) {
                const int v0 = nt * 128 + wn * 32 + ni * 8 + (lane & 3) * 2;
                const float a0v = __ldg(avec + v0);
                const float a1v = __ldg(avec + v0 + 1);
                float h00 = ftanh(acc[mi][ni][0]);
                float h01 = ftanh(acc[mi][ni][1]);
                float h10 = ftanh(acc[mi][ni][2]);
                float h11 = ftanh(acc[mi][ni][3]);
                g_h2[(rowbase + r0) * 192 + (v0 >> 1)]     = h2_bits(h00, h01);
                g_h2[(rowbase + r0 + 8) * 192 + (v0 >> 1)] = h2_bits(h10, h11);
                sc[mi][0] += h00 * a0v + h01 * a1v;
                sc[mi][1] += h10 * a0v + h11 * a1v;
            }
        }
    }

    // ---- score reduction: quad shfl, then cross-warp over wn=0..3 ----
    #pragma unroll
    for (int mi = 0; mi < 2; ++mi)
        #pragma unroll
        for (int j = 0; j < 2; ++j) {
            float s = sc[mi][j];
            s += __shfl_xor_sync(0xFFFFFFFFu, s, 1);
            s += __shfl_xor_sync(0xFFFFFFFFu, s, 2);
            sc[mi][j] = s;
        }
    __syncthreads();
    if (wn > 0 && (lane & 3) == 0) {
        #pragma unroll
        for (int mi = 0; mi < 2; ++mi)
            #pragma unroll
            for (int j = 0; j < 2; ++j)
                red[(wn - 1) * 64 + wm * 32 + mi * 16 + j * 8 + (lane >> 2)] =
                    sc[mi][j];
    }
    __syncthreads();
    if (wn == 0 && (lane & 3) == 0) {
        #pragma unroll
        for (int mi = 0; mi < 2; ++mi)
            #pragma unroll
            for (int j = 0; j < 2; ++j) {
                int lr = wm * 32 + mi * 16 + j * 8 + (lane >> 2);
                // fixed summation order: deterministic
                g_scores[rowbase + lr] =
                    sc[mi][j] + red[lr] + red[64 + lr] + red[128 + lr];
            }
    }
}

// ================= kernel 2: softmax over C + weighted sum ==================
__global__ void __launch_bounds__(cfg::CV)
k2_softmax_kernel(float* __restrict__ out) {
    using namespace cfg;
    const int b = blockIdx.x;
    const int tid = threadIdx.x;

    __shared__ float scs[C];
    __shared__ float attn[C];
    __shared__ float red[32];
    __shared__ float s_max, s_sum;

    if (tid < C) scs[tid] = g_scores[b * C + tid];
    __syncthreads();

    if (tid < 32) {
        float m = -3.4e38f;
        for (int c = tid; c < C; c += 32) m = fmaxf(m, scs[c]);
        red[tid] = m;
    }
    __syncthreads();
    if (tid == 0) {
        float m = red[0];
        #pragma unroll
        for (int j = 1; j < 32; ++j) m = fmaxf(m, red[j]);
        s_max = m;
    }
    __syncthreads();
    if (tid < 32) {
        float s = 0.f;
        for (int c = tid; c < C; c += 32) s += expf(scs[c] - s_max);
        red[tid] = s;
    }
    __syncthreads();
    if (tid == 0) {
        float s = 0.f;
        #pragma unroll
        for (int j = 0; j < 32; ++j) s += red[j];
        s_sum = s;
    }
    __syncthreads();
    if (tid < C) attn[tid] = expf(scs[tid] - s_max) / s_sum;
    __syncthreads();

    // h stored as half; read per-v halves (coalesced 768B rows)
    const __half* hb = (const __half*)g_h2 + (size_t)b * C * CV;
    const int v = tid;
    float a0 = 0.f, a1 = 0.f, a2 = 0.f, a3 = 0.f;
    #pragma unroll 4
    for (int c = 0; c < C; c += 4) {
        a0 = fmaf(attn[c + 0], __half2float(hb[(size_t)(c + 0) * CV + v]), a0);
        a1 = fmaf(attn[c + 1], __half2float(hb[(size_t)(c + 1) * CV + v]), a1);
        a2 = fmaf(attn[c + 2], __half2float(hb[(size_t)(c + 2) * CV + v]), a2);
        a3 = fmaf(attn[c + 3], __half2float(hb[(size_t)(c + 3) * CV + v]), a3);
    }
    out[(size_t)b * CV + v] = (a0 + a1) + (a2 + a3);
}

// ================================ launch =====================================
extern "C" void kernel_launch(void* const* d_in, const int* in_sizes, int n_in,
                              void* d_out, int out_size) {
    (void)in_sizes; (void)n_in; (void)out_size;
    const int*   starts   = (const int*)d_in[0];
    const int*   paths    = (const int*)d_in[1];
    const int*   ends     = (const int*)d_in[2];
    /* masks d_in[3] unused by the reference */
    const float* node_emb = (const float*)d_in[4];
    const float* path_emb = (const float*)d_in[5];
    const float* W        = (const float*)d_in[6];
    const float* avec     = (const float*)d_in[7];
    float* out = (float*)d_out;

    cudaFuncSetAttribute(k1_mma_kernel,
                         cudaFuncAttributeMaxDynamicSharedMemorySize,
                         (int)cfg::SMEM_BYTES);

    wconv_kernel<<<cfg::CV * cfg::F / 4 / 256, 256>>>(W);
    k1_mma_kernel<<<cfg::NTILES, cfg::NTH, cfg::SMEM_BYTES>>>(
        starts, paths, ends, node_emb, path_emb, avec);
    k2_softmax_kernel<<<cfg::B, cfg::CV>>>(out);
}

// round 12
// speedup vs baseline: 4.8983x; 1.0113x over previous
#include <cuda_runtime.h>
#include <cuda_fp16.h>
#include <cstdint>
#include <cstddef>

// ============================ problem constants =============================
namespace cfg {
constexpr int B  = 512;
constexpr int C  = 200;
constexpr int E  = 128;
constexpr int CV = 384;
constexpr int F  = 384;                 // K dim (3E)
constexpr int ROWS = B * C;             // 102400
constexpr int MT = 64;                  // rows per CTA tile
constexpr int NTILES = ROWS / MT;       // 1600
constexpr int NTH = 256;                // 8 warps: 2 (M) x 4 (N)

constexpr int APAD = 392;               // A row: 384 + 8 fp16 -> 784 B
constexpr int BPAD = 40;                // B row: 32 + 8 fp16  -> 80 B

// dynamic smem layout (bytes)
constexpr uint32_t A_OFF = 0;            // [64][392] fp16 = 50176
constexpr uint32_t B0    = 50176;        // [128][40] fp16 = 10240
constexpr uint32_t B1    = 60416;        // 10240
constexpr uint32_t IDX   = 70656;        // 192 ints = 768
constexpr uint32_t RED   = 71424;        // 3 x 64 floats = 768
constexpr uint32_t SMEM_BYTES = 72192;   // x3 CTAs = 216576 <= 227KB SM budget
constexpr int NCHUNK = 36;               // 3 nt x 12 kc
}

// ===================== device scratch (no runtime alloc) ====================
__device__ __half    g_Wf16[cfg::CV * cfg::F];       // W fp16, [v][k] row-major
__device__ uint32_t  g_h2[(size_t)cfg::ROWS * cfg::CV / 2];  // h as half2 pairs
__device__ float     g_scores[cfg::ROWS];

// ============================== PTX helpers =================================
__device__ __forceinline__ uint32_t smem_u32(const void* p) {
    uint32_t a;
    asm("{ .reg .u64 t; cvta.to.shared.u64 t, %1; cvt.u32.u64 %0, t; }" : "=r"(a) : "l"(p));
    return a;
}
__device__ __forceinline__ void ldsm_x4(uint32_t (&r)[4], uint32_t addr) {
    asm volatile("ldmatrix.sync.aligned.m8n8.x4.shared.b16 {%0,%1,%2,%3}, [%4];"
                 : "=r"(r[0]), "=r"(r[1]), "=r"(r[2]), "=r"(r[3]) : "r"(addr));
}
__device__ __forceinline__ void mma_f16(float (&d)[4], const uint32_t (&a)[4],
                                        uint32_t b0, uint32_t b1) {
    asm volatile(
        "mma.sync.aligned.m16n8k16.row.col.f32.f16.f16.f32 "
        "{%0,%1,%2,%3}, {%4,%5,%6,%7}, {%8,%9}, {%0,%1,%2,%3};"
        : "+f"(d[0]), "+f"(d[1]), "+f"(d[2]), "+f"(d[3])
        : "r"(a[0]), "r"(a[1]), "r"(a[2]), "r"(a[3]), "r"(b0), "r"(b1));
}
__device__ __forceinline__ void cp_async16(uint32_t dst, const void* src) {
    asm volatile("cp.async.cg.shared.global [%0], [%1], 16;"
                 :: "r"(dst), "l"(src) : "memory");
}
__device__ __forceinline__ void cp_commit() {
    asm volatile("cp.async.commit_group;" ::: "memory");
}
__device__ __forceinline__ void cp_wait1() {
    asm volatile("cp.async.wait_group 1;" ::: "memory");
}
__device__ __forceinline__ uint32_t h2_bits(float lo, float hi) {
    __half2 h = __floats2half2_rn(lo, hi);
    return *(uint32_t*)&h;
}
// fast branchless tanh: MUFU.EX2 + fast divide, abs err ~1e-6
__device__ __forceinline__ float ftanh(float x) {
    x = fminf(fmaxf(x, -15.f), 15.f);
    float t = __expf(2.f * x);
    return __fdividef(t - 1.f, t + 1.f);
}

// ================= kernel 0: W fp32 -> fp16 ([v][k] row-major) ==============
__global__ void __launch_bounds__(256)
wconv_kernel(const float* __restrict__ W) {
    int i = blockIdx.x * 256 + threadIdx.x;          // float4 id, 36864 total
    float4 x = ((const float4*)W)[i];
    ((uint2*)g_Wf16)[i] = make_uint2(h2_bits(x.x, x.y), h2_bits(x.z, x.w));
}

// ====== kernel 1: gather + fp16 HMMA GEMM + tanh + h + scores ===============
__global__ void __launch_bounds__(cfg::NTH, 3)
k1_mma_kernel(const int* __restrict__ starts,
              const int* __restrict__ paths,
              const int* __restrict__ ends,
              const float* __restrict__ node_emb,
              const float* __restrict__ path_emb,
              const float* __restrict__ avec) {
    using namespace cfg;
    extern __shared__ char smem[];
    const uint32_t sb = smem_u32(smem);
    const int tid = threadIdx.x;
    const int wid = tid >> 5, lane = tid & 31;
    const int wm = wid & 1;              // M slice (32 rows)
    const int wn = wid >> 1;             // N slice (32 cols of 128-chunk)
    const int tile = blockIdx.x;
    int* sidx = (int*)(smem + IDX);
    float* red = (float*)(smem + RED);   // [3][64]

    // ---- indices (64 rows x 3) ----
    if (tid < 192) {
        int seg = tid >> 6, r = tid & 63;
        const int* p = (seg == 0) ? starts : (seg == 1) ? paths : ends;
        sidx[tid] = p[tile * 64 + r];
    }
    __syncthreads();

    // ---- B chunk staging: [128 n][32 k] fp16 = 512 x 16B, 2 per thread ----
    auto stageB = [&](int q, uint32_t buf) {
        const int nt = q / 12, kc = q % 12;
        #pragma unroll
        for (int i = 0; i < 2; ++i) {
            int t = tid + i * 256;                   // 0..511
            int n = t >> 2, ch = t & 3;              // row, 16B chunk (8 fp16)
            const __half* src = g_Wf16 +
                ((size_t)(nt * 128 + n) * 384 + kc * 32 + ch * 8);
            cp_async16(sb + buf + (uint32_t)n * (BPAD * 2) + (uint32_t)ch * 16, src);
        }
        cp_commit();
    };
    stageB(0, B0);                                   // overlaps gather

    // ---- gather ctx rows -> fp16 into padded A (per-seg: no div/mod) ----
    #pragma unroll
    for (int seg = 0; seg < 3; ++seg) {
        const float4* src = (seg == 1) ? (const float4*)path_emb
                                       : (const float4*)node_emb;
        #pragma unroll 2
        for (int i = 0; i < 8; ++i) {
            int task = tid + i * 256;                // 0..2047
            int row = task >> 5, j = task & 31;
            int idx = sidx[seg * 64 + row];
            float4 x = __ldg(src + (size_t)idx * 32 + j);
            int k = seg * 128 + j * 4;
            *(uint2*)(smem + A_OFF + (uint32_t)row * (APAD * 2) + (uint32_t)k * 2) =
                make_uint2(h2_bits(x.x, x.y), h2_bits(x.z, x.w));
        }
    }
    __syncthreads();
    stageB(1, B1);

    // ---- ldmatrix lane addresses ----
    const uint32_t a_lane = sb + A_OFF + (uint32_t)(wm * 32 + (lane & 15)) * (APAD * 2)
                          + (uint32_t)(lane >> 4) * 16;
    const int bgrp = lane >> 3;
    const uint32_t b_lane = (uint32_t)(((bgrp & 2) << 2) + (lane & 7)) * (BPAD * 2)
                          + (uint32_t)(bgrp & 1) * 16;

    float sc[2][2] = {{0.f, 0.f}, {0.f, 0.f}};       // score partials [mi][rowhalf]
    const size_t rowbase = (size_t)tile * 64;

    for (int nt = 0; nt < 3; ++nt) {
        float acc[2][4][4];
        #pragma unroll
        for (int mi = 0; mi < 2; ++mi)
            #pragma unroll
            for (int ni = 0; ni < 4; ++ni)
                #pragma unroll
                for (int q = 0; q < 4; ++q) acc[mi][ni][q] = 0.f;

        for (int kc = 0; kc < 12; ++kc) {
            const int q = nt * 12 + kc;
            const uint32_t buf = sb + ((q & 1) ? B1 : B0);
            // One group committed per iteration (real stage or empty commit),
            // so wait_group 1 provably drains chunk q's group (R8 tail fix).
            cp_wait1();
            __syncthreads();

            #pragma unroll
            for (int s = 0; s < 2; ++s) {            // two k16 steps
                const uint32_t akoff = (uint32_t)(kc * 32 + s * 16) * 2;
                uint32_t a[2][4];
                #pragma unroll
                for (int mi = 0; mi < 2; ++mi)
                    ldsm_x4(a[mi], a_lane + mi * (16 * APAD * 2) + akoff);
                #pragma unroll
                for (int bj = 0; bj < 2; ++bj) {
                    const uint32_t bn = (uint32_t)(wn * 32 + bj * 16) * (BPAD * 2)
                                      + (uint32_t)(s * 32);
                    uint32_t r[4];
                    ldsm_x4(r, buf + b_lane + bn);
                    #pragma unroll
                    for (int mi = 0; mi < 2; ++mi) {
                        mma_f16(acc[mi][2*bj],   a[mi], r[0], r[1]);
                        mma_f16(acc[mi][2*bj+1], a[mi], r[2], r[3]);
                    }
                }
            }

            __syncthreads();                         // reads of buf done
            if (q + 2 < NCHUNK) stageB(q + 2, (q & 1) ? B1 : B0);
            else                cp_commit();         // empty group, keep depth
        }

        // ---- epilogue: fast tanh, half2 h store, score partials ----
        #pragma unroll
        for (int mi = 0; mi < 2; ++mi) {
            const int r0 = wm * 32 + mi * 16 + (lane >> 2);
            #pragma unroll
            for (int ni = 0; ni < 4; ++ni) {
                const int v0 = nt * 128 + wn * 32 + ni * 8 + (lane & 3) * 2;
                const float a0v = __ldg(avec + v0);
                const float a1v = __ldg(avec + v0 + 1);
                float h00 = ftanh(acc[mi][ni][0]);
                float h01 = ftanh(acc[mi][ni][1]);
                float h10 = ftanh(acc[mi][ni][2]);
                float h11 = ftanh(acc[mi][ni][3]);
                g_h2[(rowbase + r0) * 192 + (v0 >> 1)]     = h2_bits(h00, h01);
                g_h2[(rowbase + r0 + 8) * 192 + (v0 >> 1)] = h2_bits(h10, h11);
                sc[mi][0] += h00 * a0v + h01 * a1v;
                sc[mi][1] += h10 * a0v + h11 * a1v;
            }
        }
    }

    // ---- score reduction: quad shfl, then cross-warp over wn=0..3 ----
    #pragma unroll
    for (int mi = 0; mi < 2; ++mi)
        #pragma unroll
        for (int j = 0; j < 2; ++j) {
            float s = sc[mi][j];
            s += __shfl_xor_sync(0xFFFFFFFFu, s, 1);
            s += __shfl_xor_sync(0xFFFFFFFFu, s, 2);
            sc[mi][j] = s;
        }
    __syncthreads();
    if (wn > 0 && (lane & 3) == 0) {
        #pragma unroll
        for (int mi = 0; mi < 2; ++mi)
            #pragma unroll
            for (int j = 0; j < 2; ++j)
                red[(wn - 1) * 64 + wm * 32 + mi * 16 + j * 8 + (lane >> 2)] =
                    sc[mi][j];
    }
    __syncthreads();
    if (wn == 0 && (lane & 3) == 0) {
        #pragma unroll
        for (int mi = 0; mi < 2; ++mi)
            #pragma unroll
            for (int j = 0; j < 2; ++j) {
                int lr = wm * 32 + mi * 16 + j * 8 + (lane >> 2);
                // fixed summation order: deterministic
                g_scores[rowbase + lr] =
                    sc[mi][j] + red[lr] + red[64 + lr] + red[128 + lr];
            }
    }
}

// ======= kernel 2: softmax over C + weighted sum (LDG.64, reverse-b) ========
__global__ void __launch_bounds__(cfg::CV)
k2_softmax_kernel(float* __restrict__ out) {
    using namespace cfg;
    // Reverse order: first blocks read the h rows k1 wrote LAST (L2-hot).
    const int b = (B - 1) - blockIdx.x;
    const int tid = threadIdx.x;

    __shared__ float scs[C];
    __shared__ float attn[C];
    __shared__ float red[32];
    __shared__ float sred[4 * CV];       // cross-phase partials, 6 KB
    __shared__ float s_max, s_sum;

    if (tid < C) scs[tid] = g_scores[b * C + tid];
    __syncthreads();

    if (tid < 32) {
        float m = -3.4e38f;
        for (int c = tid; c < C; c += 32) m = fmaxf(m, scs[c]);
        red[tid] = m;
    }
    __syncthreads();
    if (tid == 0) {
        float m = red[0];
        #pragma unroll
        for (int j = 1; j < 32; ++j) m = fmaxf(m, red[j]);
        s_max = m;
    }
    __syncthreads();
    if (tid < 32) {
        float s = 0.f;
        for (int c = tid; c < C; c += 32) s += expf(scs[c] - s_max);
        red[tid] = s;
    }
    __syncthreads();
    if (tid == 0) {
        float s = 0.f;
        #pragma unroll
        for (int j = 0; j < 32; ++j) s += red[j];
        s_sum = s;
    }
    __syncthreads();
    if (tid < C) attn[tid] = expf(scs[tid] - s_max) / s_sum;
    __syncthreads();

    // Weighted sum: h rows are 384 halves = 96 uint2 (LDG.64) per c.
    // Thread layout: vq = tid % 96 (owns v = 4*vq..4*vq+3), phase cg = tid/96
    // handles c = cg, cg+4, ... (50 iterations). Coalesced 768B per c-row.
    const int vq = tid % 96;
    const int cg = tid / 96;             // 0..3
    const uint2* hb = (const uint2*)g_h2 + (size_t)b * C * 96;

    float a0 = 0.f, a1 = 0.f, a2 = 0.f, a3 = 0.f;
    #pragma unroll 2
    for (int c = cg; c < C; c += 4) {
        const float w = attn[c];
        uint2 d = __ldg(hb + (size_t)c * 96 + vq);
        __half2 p0 = *(__half2*)&d.x;
        __half2 p1 = *(__half2*)&d.y;
        float2 f0 = __half22float2(p0);
        float2 f1 = __half22float2(p1);
        a0 = fmaf(w, f0.x, a0);
        a1 = fmaf(w, f0.y, a1);
        a2 = fmaf(w, f1.x, a2);
        a3 = fmaf(w, f1.y, a3);
    }
    sred[cg * CV + vq * 4 + 0] = a0;
    sred[cg * CV + vq * 4 + 1] = a1;
    sred[cg * CV + vq * 4 + 2] = a2;
    sred[cg * CV + vq * 4 + 3] = a3;
    __syncthreads();

    // final: one thread per v, fixed summation order (deterministic)
    const int v = tid;
    out[(size_t)b * CV + v] = (sred[v] + sred[CV + v]) +
                              (sred[2 * CV + v] + sred[3 * CV + v]);
}

// ================================ launch =====================================
extern "C" void kernel_launch(void* const* d_in, const int* in_sizes, int n_in,
                              void* d_out, int out_size) {
    (void)in_sizes; (void)n_in; (void)out_size;
    const int*   starts   = (const int*)d_in[0];
    const int*   paths    = (const int*)d_in[1];
    const int*   ends     = (const int*)d_in[2];
    /* masks d_in[3] unused by the reference */
    const float* node_emb = (const float*)d_in[4];
    const float* path_emb = (const float*)d_in[5];
    const float* W        = (const float*)d_in[6];
    const float* avec     = (const float*)d_in[7];
    float* out = (float*)d_out;

    cudaFuncSetAttribute(k1_mma_kernel,
                         cudaFuncAttributeMaxDynamicSharedMemorySize,
                         (int)cfg::SMEM_BYTES);

    wconv_kernel<<<cfg::CV * cfg::F / 4 / 256, 256>>>(W);
    k1_mma_kernel<<<cfg::NTILES, cfg::NTH, cfg::SMEM_BYTES>>>(
        starts, paths, ends, node_emb, path_emb, avec);
    k2_softmax_kernel<<<cfg::B, cfg::CV>>>(out);
}